// round 11
// baseline (speedup 1.0000x reference)
#include <cuda_runtime.h>
#include <cuda_bf16.h>
#include <cstdint>
#include <math.h>

#define B_   8
#define T_   512
#define D_   512
#define NH_  8
#define DH_  64

#define PLANE_ELEMS (B_ * NH_ * T_ * DH_)
__device__ __nv_bfloat16 g_Qh[PLANE_ELEMS], g_Ql[PLANE_ELEMS];   // [b][h][t][d], pre-scaled 1/8
__device__ __nv_bfloat16 g_Kh[PLANE_ELEMS], g_Kl[PLANE_ELEMS];   // [b][h][t][d]
__device__ __nv_bfloat16 g_VTh[PLANE_ELEMS], g_VTl[PLANE_ELEMS]; // [b][h][d][t]
__device__ float g_pos[NH_ * T_ * B_ * T_];                      // [h][t][b][s]

__device__ __nv_bfloat16 g_Xh[4096 * 512], g_Xl[4096 * 512];
__device__ __nv_bfloat16 g_CXh[4096 * 512], g_CXl[4096 * 512];
__device__ __nv_bfloat16 g_Wqh[512 * 512], g_Wql[512 * 512];
__device__ __nv_bfloat16 g_Wkh[512 * 512], g_Wkl[512 * 512];
__device__ __nv_bfloat16 g_Wvh[512 * 512], g_Wvl[512 * 512];
__device__ __nv_bfloat16 g_Woh[512 * 512], g_Wol[512 * 512];

__device__ __forceinline__ void cp16(unsigned smem_addr, const void* g) {
    asm volatile("cp.async.cg.shared.global [%0], [%1], 16;\n" :: "r"(smem_addr), "l"(g));
}
__device__ __forceinline__ void cp_commit() { asm volatile("cp.async.commit_group;\n"); }
template <int N> __device__ __forceinline__ void cp_wait() {
    asm volatile("cp.async.wait_group %0;\n" :: "n"(N));
}
__device__ __forceinline__ unsigned pack2(__nv_bfloat16 x, __nv_bfloat16 y) {
    __nv_bfloat162 t; t.x = x; t.y = y;
    return *reinterpret_cast<unsigned*>(&t);
}
__device__ __forceinline__ void split2(float x, float y, unsigned& hi, unsigned& lo) {
    __nv_bfloat16 xh = __float2bfloat16(x), yh = __float2bfloat16(y);
    hi = pack2(xh, yh);
    lo = pack2(__float2bfloat16(x - __bfloat162float(xh)),
               __float2bfloat16(y - __bfloat162float(yh)));
}
__device__ __forceinline__ void mma16816(float& c0, float& c1, float& c2, float& c3,
                                         unsigned a0, unsigned a1, unsigned a2, unsigned a3,
                                         unsigned b0, unsigned b1) {
    asm volatile("mma.sync.aligned.m16n8k16.row.col.f32.bf16.bf16.f32 "
                 "{%0,%1,%2,%3},{%4,%5,%6,%7},{%8,%9},{%0,%1,%2,%3};\n"
                 : "+f"(c0), "+f"(c1), "+f"(c2), "+f"(c3)
                 : "r"(a0), "r"(a1), "r"(a2), "r"(a3), "r"(b0), "r"(b1));
}
__device__ __forceinline__ void ldsm4(unsigned& r0, unsigned& r1, unsigned& r2, unsigned& r3,
                                      unsigned a) {
    asm volatile("ldmatrix.sync.aligned.m8n8.x4.shared.b16 {%0,%1,%2,%3}, [%4];\n"
                 : "=r"(r0), "=r"(r1), "=r"(r2), "=r"(r3) : "r"(a));
}

// ---------------------------------------------------------------------------
// split x + 4 weights into bf16 hi/lo planes (once)
// ---------------------------------------------------------------------------
__global__ __launch_bounds__(256) void split_kernel(const float* __restrict__ x,
                                                    const float* __restrict__ Wq,
                                                    const float* __restrict__ Wk,
                                                    const float* __restrict__ Wv,
                                                    const float* __restrict__ Wo) {
    const int seg = blockIdx.y;
    const float* src;
    __nv_bfloat16 *dh, *dl;
    int n;
    if (seg == 0)      { src = x;  dh = g_Xh;  dl = g_Xl;  n = 4096 * 512 / 2; }
    else if (seg == 1) { src = Wq; dh = g_Wqh; dl = g_Wql; n = 512 * 512 / 2; }
    else if (seg == 2) { src = Wk; dh = g_Wkh; dl = g_Wkl; n = 512 * 512 / 2; }
    else if (seg == 3) { src = Wv; dh = g_Wvh; dl = g_Wvl; n = 512 * 512 / 2; }
    else               { src = Wo; dh = g_Woh; dl = g_Wol; n = 512 * 512 / 2; }
    for (int i = blockIdx.x * 256 + threadIdx.x; i < n; i += gridDim.x * 256) {
        float2 v = ((const float2*)src)[i];
        unsigned hi, lo;
        split2(v.x, v.y, hi, lo);
        ((unsigned*)dh)[i] = hi;
        ((unsigned*)dl)[i] = lo;
    }
}

// ---------------------------------------------------------------------------
// bf16-plane GEMM with ldmatrix fragments. OUT=0: QKV fused (blockIdx.z picks
// W/bias/epilogue). OUT=1: output projection (ctx @ Wo^T + bo -> fp32).
// CTA 128x64, 256 thr (2x4 warps), k-chunk 64, cp.async 2-stage.
// ---------------------------------------------------------------------------
#define GA_STR 72
#define GA_PLB (128 * GA_STR * 2)
#define SA_BUF (2 * GA_PLB)
#define GW_PLB (64 * GA_STR * 2)
#define SW_BUF (2 * GW_PLB)
#define SW_B   (2 * SA_BUF)
#define GSM_BYTES (SW_B + 2 * SW_BUF)

template <int OUT>
__global__ __launch_bounds__(256) void qkv_gemm(const float* __restrict__ bq,
                                                const float* __restrict__ bk,
                                                const float* __restrict__ bv,
                                                float* __restrict__ Cout) {
    extern __shared__ char gsm[];
    const unsigned sb = (unsigned)__cvta_generic_to_shared(gsm);
    const int mode = OUT ? 3 : blockIdx.z;

    const __nv_bfloat16 *Aph, *Apl, *Wph, *Wpl;
    const float* bias;
    if (OUT) { Aph = g_CXh; Apl = g_CXl; Wph = g_Woh; Wpl = g_Wol; bias = bq; }
    else {
        Aph = g_Xh; Apl = g_Xl;
        if (mode == 0)      { Wph = g_Wqh; Wpl = g_Wql; bias = bq; }
        else if (mode == 1) { Wph = g_Wkh; Wpl = g_Wkl; bias = bk; }
        else                { Wph = g_Wvh; Wpl = g_Wvl; bias = bv; }
    }

    const int i0 = blockIdx.x * 128, j0 = blockIdx.y * 64;
    const int tid = threadIdx.x;
    const int wid = tid >> 5, lane = tid & 31;
    const int wm = wid & 1, wn = wid >> 1;
    const int grp = lane >> 2, q = lane & 3;
    const int mat = lane >> 3, mr = lane & 7;

    // ldmatrix source offsets (bytes)
    const unsigned aoff = ((wm * 64 + (mat & 1) * 8 + mr) * GA_STR + (mat >> 1) * 8) * 2;
    const unsigned boff = ((wn * 16 + (mat >> 1) * 8 + mr) * GA_STR + (mat & 1) * 8) * 2;

    auto issue = [&](int st, int buf) {
        const int k0 = st * 64;
        for (int c = tid; c < 2048; c += 256) {
            int col8 = c & 7, row = (c >> 3) & 127, pl = c >> 10;
            const __nv_bfloat16* src = (pl ? Apl : Aph) + (size_t)(i0 + row) * 512 + k0 + col8 * 8;
            cp16(sb + buf * SA_BUF + pl * GA_PLB + (row * GA_STR + col8 * 8) * 2, src);
        }
        for (int c = tid; c < 1024; c += 256) {
            int col8 = c & 7, row = (c >> 3) & 63, pl = c >> 9;
            const __nv_bfloat16* src = (pl ? Wpl : Wph) + (size_t)(j0 + row) * 512 + k0 + col8 * 8;
            cp16(sb + SW_B + buf * SW_BUF + pl * GW_PLB + (row * GA_STR + col8 * 8) * 2, src);
        }
    };

    issue(0, 0); cp_commit();
    issue(1, 1); cp_commit();

    float acc[4][2][4];
#pragma unroll
    for (int a = 0; a < 4; a++)
#pragma unroll
        for (int b = 0; b < 2; b++)
#pragma unroll
            for (int c = 0; c < 4; c++) acc[a][b][c] = 0.f;

    for (int st = 0; st < 8; st++) {
        const int buf = st & 1;
        if (st == 7) cp_wait<0>(); else cp_wait<1>();
        __syncthreads();

        const unsigned Ab = sb + buf * SA_BUF;
        const unsigned Wb = sb + SW_B + buf * SW_BUF;
#pragma unroll
        for (int k16 = 0; k16 < 4; k16++) {
            unsigned bh[2][2], bl[2][2];
            ldsm4(bh[0][0], bh[0][1], bh[1][0], bh[1][1], Wb + boff + k16 * 32);
            ldsm4(bl[0][0], bl[0][1], bl[1][0], bl[1][1], Wb + GW_PLB + boff + k16 * 32);
#pragma unroll
            for (int mf = 0; mf < 4; mf++) {
                unsigned a0, a1, a2, a3, c0, c1, c2, c3;
                const unsigned ad = Ab + aoff + mf * (16 * GA_STR * 2) + k16 * 32;
                ldsm4(a0, a1, a2, a3, ad);
                ldsm4(c0, c1, c2, c3, ad + GA_PLB);
#pragma unroll
                for (int nf = 0; nf < 2; nf++) {
                    mma16816(acc[mf][nf][0], acc[mf][nf][1], acc[mf][nf][2], acc[mf][nf][3],
                             a0, a1, a2, a3, bh[nf][0], bh[nf][1]);
                    mma16816(acc[mf][nf][0], acc[mf][nf][1], acc[mf][nf][2], acc[mf][nf][3],
                             a0, a1, a2, a3, bl[nf][0], bl[nf][1]);
                    mma16816(acc[mf][nf][0], acc[mf][nf][1], acc[mf][nf][2], acc[mf][nf][3],
                             c0, c1, c2, c3, bh[nf][0], bh[nf][1]);
                }
            }
        }
        __syncthreads();
        if (st + 2 < 8) issue(st + 2, buf);
        cp_commit();
    }

#pragma unroll
    for (int mf = 0; mf < 4; mf++) {
#pragma unroll
        for (int nf = 0; nf < 2; nf++) {
#pragma unroll
            for (int half = 0; half < 2; half++) {
                const int i = i0 + wm * 64 + mf * 16 + grp + half * 8;
                const int j = j0 + wn * 16 + nf * 8 + 2 * q;
                float v0 = acc[mf][nf][half * 2]     + bias[j];
                float v1 = acc[mf][nf][half * 2 + 1] + bias[j + 1];
                if (OUT) {
                    *(float2*)&Cout[(size_t)i * 512 + j] = make_float2(v0, v1);
                    continue;
                }
                if (mode == 0) { v0 *= 0.125f; v1 *= 0.125f; }
                const int b = i >> 9, t = i & 511;
                const int hh = j >> 6, dh = j & 63;
                if (mode == 0 || mode == 1) {
                    unsigned hi, lo;
                    split2(v0, v1, hi, lo);
                    size_t o = ((size_t)(b * NH_ + hh) * T_ + t) * 64 + dh;
                    if (mode == 0) { *(unsigned*)&g_Qh[o] = hi; *(unsigned*)&g_Ql[o] = lo; }
                    else           { *(unsigned*)&g_Kh[o] = hi; *(unsigned*)&g_Kl[o] = lo; }
                } else {
                    __nv_bfloat16 h0 = __float2bfloat16(v0);
                    __nv_bfloat16 h1 = __float2bfloat16(v1);
                    size_t o = ((size_t)(b * NH_ + hh) * 64 + dh) * T_ + t;
                    g_VTh[o]       = h0;
                    g_VTh[o + T_]  = h1;
                    g_VTl[o]       = __float2bfloat16(v0 - __bfloat162float(h0));
                    g_VTl[o + T_]  = __float2bfloat16(v1 - __bfloat162float(h1));
                }
            }
        }
    }
}

// ---------------------------------------------------------------------------
// pos kernel (unchanged)
// ---------------------------------------------------------------------------
#define PR_STR 68
#define PTILE  (64 * PR_STR)

__global__ __launch_bounds__(128) void pos_kernel(const float* __restrict__ rel) {
    __shared__ float Rs[2 * PTILE];
    const int t = blockIdx.x, h = blockIdx.y;
    const int tid = threadIdx.x;
    const int wid = tid >> 5, lane = tid & 31;
    const int grp = lane >> 2, q = lane & 3;
    const unsigned sb = (unsigned)__cvta_generic_to_shared(Rs);

    unsigned Bh[4][2], Bl[4][2];
#pragma unroll
    for (int kk = 0; kk < 4; kk++) {
        size_t base = ((size_t)(grp*NH_+h)*T_ + t)*64 + kk*16 + 2*q;
        Bh[kk][0] = *(const unsigned*)&g_Qh[base];
        Bh[kk][1] = *(const unsigned*)&g_Qh[base + 8];
        Bl[kk][0] = *(const unsigned*)&g_Ql[base];
        Bl[kk][1] = *(const unsigned*)&g_Ql[base + 8];
    }

    auto issue = [&](int blk, int buf) {
        const float* base = rel + ((size_t)t*T_ + blk*64)*D_ + h*64;
#pragma unroll
        for (int p = 0; p < 8; p++) {
            int c = tid + p * 128;
            int row = c >> 4, col4 = c & 15;
            cp16(sb + (unsigned)(buf*PTILE + row*PR_STR + col4*4)*4,
                 base + (size_t)row*D_ + col4*4);
        }
    };

    issue(0, 0); cp_commit();
    issue(1, 1); cp_commit();

    for (int blk = 0; blk < 8; blk++) {
        const int buf = blk & 1;
        if (blk == 7) cp_wait<0>(); else cp_wait<1>();
        __syncthreads();

        const float* rs = Rs + buf*PTILE + (wid*16 + grp)*PR_STR;
        float c0 = 0.f, c1 = 0.f, c2 = 0.f, c3 = 0.f;
#pragma unroll
        for (int kk = 0; kk < 4; kk++) {
            float2 rA0 = *(const float2*)(rs + kk*16 + 2*q);
            float2 rA2 = *(const float2*)(rs + kk*16 + 2*q + 8);
            float2 rA1 = *(const float2*)(rs + 8*PR_STR + kk*16 + 2*q);
            float2 rA3 = *(const float2*)(rs + 8*PR_STR + kk*16 + 2*q + 8);
            unsigned ah0, al0, ah1, al1, ah2, al2, ah3, al3;
            split2(rA0.x, rA0.y, ah0, al0);
            split2(rA1.x, rA1.y, ah1, al1);
            split2(rA2.x, rA2.y, ah2, al2);
            split2(rA3.x, rA3.y, ah3, al3);
            mma16816(c0,c1,c2,c3, ah0,ah1,ah2,ah3, Bh[kk][0], Bh[kk][1]);
            mma16816(c0,c1,c2,c3, ah0,ah1,ah2,ah3, Bl[kk][0], Bl[kk][1]);
            mma16816(c0,c1,c2,c3, al0,al1,al2,al3, Bh[kk][0], Bh[kk][1]);
        }
        const int s0 = blk * 64 + wid * 16;
        size_t o = ((size_t)h*T_ + t) * B_;
        g_pos[(o + 2*q    )*T_ + s0 + grp    ] = c0;
        g_pos[(o + 2*q + 1)*T_ + s0 + grp    ] = c1;
        g_pos[(o + 2*q    )*T_ + s0 + grp + 8] = c2;
        g_pos[(o + 2*q + 1)*T_ + s0 + grp + 8] = c3;

        __syncthreads();
        if (blk + 2 < 8) issue(blk + 2, buf);
        cp_commit();
    }
}

// ---------------------------------------------------------------------------
// FA2 attention (unchanged from R10)
// ---------------------------------------------------------------------------
#define KS_B   0
#define KBUF_B 36864
#define KPL_B  18432
#define VS_B   73728
#define VBUF_B 49152
#define VPL_B  24576
#define PS_B   172032
#define PBUF_B 16384
#define SMEM_BYTES 204800

__global__ __launch_bounds__(256, 1) void attn_mma() {
    const int h  = blockIdx.y;
    const int t0 = blockIdx.x * 32;
    extern __shared__ char sm[];
    const unsigned sb = (unsigned)__cvta_generic_to_shared(sm);

    const int tid = threadIdx.x;
    const int wid = tid >> 5;
    const int lane = tid & 31;
    const int grp = lane >> 2, q = lane & 3;

    unsigned QAh[2][4][4], QAl[2][4][4];
#pragma unroll
    for (int mt = 0; mt < 2; mt++)
#pragma unroll
    for (int kk = 0; kk < 4; kk++) {
        size_t base = ((size_t)(wid*NH_+h)*T_ + t0 + mt*16 + grp)*64 + kk*16 + 2*q;
        QAh[mt][kk][0] = *(const unsigned*)&g_Qh[base];
        QAh[mt][kk][1] = *(const unsigned*)&g_Qh[base + 8*64];
        QAh[mt][kk][2] = *(const unsigned*)&g_Qh[base + 8];
        QAh[mt][kk][3] = *(const unsigned*)&g_Qh[base + 8*64 + 8];
        QAl[mt][kk][0] = *(const unsigned*)&g_Ql[base];
        QAl[mt][kk][1] = *(const unsigned*)&g_Ql[base + 8*64];
        QAl[mt][kk][2] = *(const unsigned*)&g_Ql[base + 8];
        QAl[mt][kk][3] = *(const unsigned*)&g_Ql[base + 8*64 + 8];
    }

    auto issue_tile = [&](int s0, int buf) {
        for (int i = tid; i < 2048; i += 256) {
            int q4 = i & 7, row = i >> 3;
            int s = row & 15, b = (row >> 4) & 7, pl = row >> 7;
            const __nv_bfloat16* src =
                (pl ? g_Kl : g_Kh) + ((size_t)(b*NH_+h)*T_ + s0 + s)*64 + q4*8;
            cp16(sb + KS_B + buf*KBUF_B + pl*KPL_B + (b*16 + s)*144 + q4*16, src);
        }
        for (int i = tid; i < 2048; i += 256) {
            int q4 = i & 1, row = i >> 1;
            int d = row & 63, b = (row >> 6) & 7, pl = row >> 9;
            const __nv_bfloat16* src =
                (pl ? g_VTl : g_VTh) + ((size_t)(b*NH_+h)*64 + d)*T_ + s0 + q4*8;
            cp16(sb + VS_B + buf*VBUF_B + pl*VPL_B + (b*64 + d)*48 + q4*16, src);
        }
        for (int i = tid; i < 1024; i += 256) {
            int q4 = i & 3, row = i >> 2;
            int t = row & 31, b = row >> 5;
            const float* src = g_pos + ((size_t)(h*T_ + t0 + t)*B_ + b)*T_ + s0 + q4*4;
            cp16(sb + PS_B + buf*PBUF_B + (b*32 + t)*64 + q4*16, src);
        }
    };

    issue_tile(0, 0);  cp_commit();
    issue_tile(16, 1); cp_commit();

    float ctx[2][8][4];
#pragma unroll
    for (int mt = 0; mt < 2; mt++)
#pragma unroll
        for (int nt = 0; nt < 8; nt++)
#pragma unroll
            for (int i = 0; i < 4; i++) ctx[mt][nt][i] = 0.f;
    float m_a[2] = {-1e30f, -1e30f}, m_b[2] = {-1e30f, -1e30f};
    float l_a[2] = {0.f, 0.f},       l_b[2] = {0.f, 0.f};

    for (int it = 0; it < 32; it++) {
        const int buf = it & 1;
        if (it == 31) cp_wait<0>(); else cp_wait<1>();
        __syncthreads();

#pragma unroll
        for (int mt = 0; mt < 2; mt++) {
            float sg[2][4];
            const float* pp = (const float*)(sm + PS_B + buf*PBUF_B) + (wid*32 + mt*16 + grp)*16;
#pragma unroll
            for (int ng = 0; ng < 2; ng++) {
                float2 pa = *(const float2*)(pp + ng*8 + 2*q);
                float2 pb = *(const float2*)(pp + 8*16 + ng*8 + 2*q);
                float c0 = pa.x, c1 = pa.y, c2 = pb.x, c3 = pb.y;
#pragma unroll
                for (int kk = 0; kk < 4; kk++) {
                    const char* kp = sm + KS_B + buf*KBUF_B + (wid*16 + ng*8 + grp)*144 + kk*32 + q*4;
                    unsigned bh0 = *(const unsigned*)kp;
                    unsigned bh1 = *(const unsigned*)(kp + 16);
                    unsigned bl0 = *(const unsigned*)(kp + KPL_B);
                    unsigned bl1 = *(const unsigned*)(kp + KPL_B + 16);
                    mma16816(c0,c1,c2,c3, QAh[mt][kk][0],QAh[mt][kk][1],QAh[mt][kk][2],QAh[mt][kk][3], bh0, bh1);
                    mma16816(c0,c1,c2,c3, QAh[mt][kk][0],QAh[mt][kk][1],QAh[mt][kk][2],QAh[mt][kk][3], bl0, bl1);
                    mma16816(c0,c1,c2,c3, QAl[mt][kk][0],QAl[mt][kk][1],QAl[mt][kk][2],QAl[mt][kk][3], bh0, bh1);
                }
                sg[ng][0] = c0; sg[ng][1] = c1; sg[ng][2] = c2; sg[ng][3] = c3;
            }

            float ma = fmaxf(fmaxf(sg[0][0], sg[0][1]), fmaxf(sg[1][0], sg[1][1]));
            float mb = fmaxf(fmaxf(sg[0][2], sg[0][3]), fmaxf(sg[1][2], sg[1][3]));
            ma = fmaxf(ma, __shfl_xor_sync(0xffffffffu, ma, 1, 4));
            ma = fmaxf(ma, __shfl_xor_sync(0xffffffffu, ma, 2, 4));
            mb = fmaxf(mb, __shfl_xor_sync(0xffffffffu, mb, 1, 4));
            mb = fmaxf(mb, __shfl_xor_sync(0xffffffffu, mb, 2, 4));
            float mna = fmaxf(m_a[mt], ma), mnb = fmaxf(m_b[mt], mb);
            float sca = __expf(m_a[mt] - mna), scb = __expf(m_b[mt] - mnb);
            float pa0 = __expf(sg[0][0] - mna), pa1 = __expf(sg[0][1] - mna);
            float pa2 = __expf(sg[1][0] - mna), pa3 = __expf(sg[1][1] - mna);
            float pb0 = __expf(sg[0][2] - mnb), pb1 = __expf(sg[0][3] - mnb);
            float pb2 = __expf(sg[1][2] - mnb), pb3 = __expf(sg[1][3] - mnb);
            float la = pa0 + pa1 + pa2 + pa3;
            float lb = pb0 + pb1 + pb2 + pb3;
            la += __shfl_xor_sync(0xffffffffu, la, 1, 4);
            la += __shfl_xor_sync(0xffffffffu, la, 2, 4);
            lb += __shfl_xor_sync(0xffffffffu, lb, 1, 4);
            lb += __shfl_xor_sync(0xffffffffu, lb, 2, 4);
            l_a[mt] = l_a[mt] * sca + la; l_b[mt] = l_b[mt] * scb + lb;
            m_a[mt] = mna; m_b[mt] = mnb;

            unsigned ah0, al0, ah1, al1, ah2, al2, ah3, al3;
            split2(pa0, pa1, ah0, al0);
            split2(pb0, pb1, ah1, al1);
            split2(pa2, pa3, ah2, al2);
            split2(pb2, pb3, ah3, al3);

#pragma unroll
            for (int nt = 0; nt < 8; nt++) {
                ctx[mt][nt][0] *= sca; ctx[mt][nt][1] *= sca;
                ctx[mt][nt][2] *= scb; ctx[mt][nt][3] *= scb;
            }
#pragma unroll
            for (int nt = 0; nt < 8; nt++) {
                const char* vp = sm + VS_B + buf*VBUF_B + (wid*64 + nt*8 + grp)*48 + q*4;
                unsigned bh0 = *(const unsigned*)vp;
                unsigned bh1 = *(const unsigned*)(vp + 16);
                unsigned bl0 = *(const unsigned*)(vp + VPL_B);
                unsigned bl1 = *(const unsigned*)(vp + VPL_B + 16);
                mma16816(ctx[mt][nt][0],ctx[mt][nt][1],ctx[mt][nt][2],ctx[mt][nt][3],
                         ah0,ah1,ah2,ah3, bh0, bh1);
                mma16816(ctx[mt][nt][0],ctx[mt][nt][1],ctx[mt][nt][2],ctx[mt][nt][3],
                         al0,al1,al2,al3, bh0, bh1);
                mma16816(ctx[mt][nt][0],ctx[mt][nt][1],ctx[mt][nt][2],ctx[mt][nt][3],
                         ah0,ah1,ah2,ah3, bl0, bl1);
            }
        }

        __syncthreads();
        if (it + 2 < 32) issue_tile((it + 2) * 16, buf);
        cp_commit();
    }

#pragma unroll
    for (int mt = 0; mt < 2; mt++) {
        const float inva = 1.0f / l_a[mt], invb = 1.0f / l_b[mt];
        size_t r0 = ((size_t)wid*T_ + t0 + mt*16 + grp)*512 + h*64 + 2*q;
        size_t r1 = r0 + 8 * 512;
#pragma unroll
        for (int nt = 0; nt < 8; nt++) {
            unsigned hi, lo;
            split2(ctx[mt][nt][0]*inva, ctx[mt][nt][1]*inva, hi, lo);
            *(unsigned*)&g_CXh[r0 + nt*8] = hi;
            *(unsigned*)&g_CXl[r0 + nt*8] = lo;
            split2(ctx[mt][nt][2]*invb, ctx[mt][nt][3]*invb, hi, lo);
            *(unsigned*)&g_CXh[r1 + nt*8] = hi;
            *(unsigned*)&g_CXl[r1 + nt*8] = lo;
        }
    }
}

// ---------------------------------------------------------------------------
extern "C" void kernel_launch(void* const* d_in, const int* in_sizes, int n_in,
                              void* d_out, int out_size) {
    const float* x   = (const float*)d_in[0];
    const float* rel = (const float*)d_in[1];
    const float* Wq  = (const float*)d_in[2];
    const float* bq  = (const float*)d_in[3];
    const float* Wk  = (const float*)d_in[4];
    const float* bk  = (const float*)d_in[5];
    const float* Wv  = (const float*)d_in[6];
    const float* bv  = (const float*)d_in[7];
    const float* Wo  = (const float*)d_in[8];
    const float* bo  = (const float*)d_in[9];
    float* out = (float*)d_out;

    cudaFuncSetAttribute(attn_mma, cudaFuncAttributeMaxDynamicSharedMemorySize, SMEM_BYTES);
    cudaFuncSetAttribute(qkv_gemm<0>, cudaFuncAttributeMaxDynamicSharedMemorySize, GSM_BYTES);
    cudaFuncSetAttribute(qkv_gemm<1>, cudaFuncAttributeMaxDynamicSharedMemorySize, GSM_BYTES);

    split_kernel<<<dim3(256, 5), 256>>>(x, Wq, Wk, Wv, Wo);

    qkv_gemm<0><<<dim3(32, 8, 3), 256, GSM_BYTES>>>(bq, bk, bv, nullptr);

    pos_kernel<<<dim3(T_, NH_), 128>>>(rel);

    attn_mma<<<dim3(T_ / 32, NH_), 256, SMEM_BYTES>>>();

    qkv_gemm<1><<<dim3(32, 8, 1), 256, GSM_BYTES>>>(bo, nullptr, nullptr, out);
}

// round 13
// speedup vs baseline: 1.2940x; 1.2940x over previous
#include <cuda_runtime.h>
#include <cuda_bf16.h>
#include <cstdint>
#include <math.h>

#define B_   8
#define T_   512
#define D_   512
#define NH_  8
#define DH_  64

#define PLANE_ELEMS (B_ * NH_ * T_ * DH_)
__device__ __nv_bfloat16 g_Qh[PLANE_ELEMS], g_Ql[PLANE_ELEMS];   // [b][h][t][d], pre-scaled 1/8
__device__ __nv_bfloat16 g_Kh[PLANE_ELEMS], g_Kl[PLANE_ELEMS];   // [b][h][t][d]
__device__ __nv_bfloat16 g_VTh[PLANE_ELEMS], g_VTl[PLANE_ELEMS]; // [b][h][d][t]
__device__ float g_pos[NH_ * T_ * B_ * T_];                      // [h][t][b][s]

__device__ __nv_bfloat16 g_Xh[4096 * 512], g_Xl[4096 * 512];
__device__ __nv_bfloat16 g_CXh[4096 * 512], g_CXl[4096 * 512];
__device__ __nv_bfloat16 g_Wqh[512 * 512], g_Wql[512 * 512];
__device__ __nv_bfloat16 g_Wkh[512 * 512], g_Wkl[512 * 512];
__device__ __nv_bfloat16 g_Wvh[512 * 512], g_Wvl[512 * 512];
__device__ __nv_bfloat16 g_Woh[512 * 512], g_Wol[512 * 512];

__device__ __forceinline__ void cp16(unsigned smem_addr, const void* g) {
    asm volatile("cp.async.cg.shared.global [%0], [%1], 16;\n" :: "r"(smem_addr), "l"(g));
}
__device__ __forceinline__ void cp_commit() { asm volatile("cp.async.commit_group;\n"); }
template <int N> __device__ __forceinline__ void cp_wait() {
    asm volatile("cp.async.wait_group %0;\n" :: "n"(N));
}
__device__ __forceinline__ unsigned pack2(__nv_bfloat16 x, __nv_bfloat16 y) {
    __nv_bfloat162 t; t.x = x; t.y = y;
    return *reinterpret_cast<unsigned*>(&t);
}
__device__ __forceinline__ void split2(float x, float y, unsigned& hi, unsigned& lo) {
    __nv_bfloat16 xh = __float2bfloat16(x), yh = __float2bfloat16(y);
    hi = pack2(xh, yh);
    lo = pack2(__float2bfloat16(x - __bfloat162float(xh)),
               __float2bfloat16(y - __bfloat162float(yh)));
}
__device__ __forceinline__ void mma16816(float& c0, float& c1, float& c2, float& c3,
                                         unsigned a0, unsigned a1, unsigned a2, unsigned a3,
                                         unsigned b0, unsigned b1) {
    asm volatile("mma.sync.aligned.m16n8k16.row.col.f32.bf16.bf16.f32 "
                 "{%0,%1,%2,%3},{%4,%5,%6,%7},{%8,%9},{%0,%1,%2,%3};\n"
                 : "+f"(c0), "+f"(c1), "+f"(c2), "+f"(c3)
                 : "r"(a0), "r"(a1), "r"(a2), "r"(a3), "r"(b0), "r"(b1));
}

// ---------------------------------------------------------------------------
// split x + 4 weights into bf16 hi/lo planes (once)
// ---------------------------------------------------------------------------
__global__ __launch_bounds__(256) void split_kernel(const float* __restrict__ x,
                                                    const float* __restrict__ Wq,
                                                    const float* __restrict__ Wk,
                                                    const float* __restrict__ Wv,
                                                    const float* __restrict__ Wo) {
    const int seg = blockIdx.y;
    const float* src;
    __nv_bfloat16 *dh, *dl;
    int n;
    if (seg == 0)      { src = x;  dh = g_Xh;  dl = g_Xl;  n = 4096 * 512 / 2; }
    else if (seg == 1) { src = Wq; dh = g_Wqh; dl = g_Wql; n = 512 * 512 / 2; }
    else if (seg == 2) { src = Wk; dh = g_Wkh; dl = g_Wkl; n = 512 * 512 / 2; }
    else if (seg == 3) { src = Wv; dh = g_Wvh; dl = g_Wvl; n = 512 * 512 / 2; }
    else               { src = Wo; dh = g_Woh; dl = g_Wol; n = 512 * 512 / 2; }
    for (int i = blockIdx.x * 256 + threadIdx.x; i < n; i += gridDim.x * 256) {
        float2 v = ((const float2*)src)[i];
        unsigned hi, lo;
        split2(v.x, v.y, hi, lo);
        ((unsigned*)dh)[i] = hi;
        ((unsigned*)dl)[i] = lo;
    }
}

// ---------------------------------------------------------------------------
// bf16-plane GEMM (reverted to R10-proven version; scalar fragment loads)
// ---------------------------------------------------------------------------
#define GA_STR 72
#define GA_PLB (128 * GA_STR * 2)
#define SA_BUF (2 * GA_PLB)
#define GW_PLB (64 * GA_STR * 2)
#define SW_BUF (2 * GW_PLB)
#define SW_B   (2 * SA_BUF)
#define GSM_BYTES (SW_B + 2 * SW_BUF)

template <int DST>
__global__ __launch_bounds__(256) void mma_gemm2(const float* __restrict__ bias,
                                                 float* __restrict__ Cout) {
    extern __shared__ char gsm[];
    const unsigned sb = (unsigned)__cvta_generic_to_shared(gsm);

    const __nv_bfloat16 *Aph, *Apl, *Wph, *Wpl;
    if (DST == 3) { Aph = g_CXh; Apl = g_CXl; } else { Aph = g_Xh; Apl = g_Xl; }
    if (DST == 0)      { Wph = g_Wqh; Wpl = g_Wql; }
    else if (DST == 1) { Wph = g_Wkh; Wpl = g_Wkl; }
    else if (DST == 2) { Wph = g_Wvh; Wpl = g_Wvl; }
    else               { Wph = g_Woh; Wpl = g_Wol; }

    const int i0 = blockIdx.x * 128, j0 = blockIdx.y * 64;
    const int tid = threadIdx.x;
    const int wid = tid >> 5, lane = tid & 31;
    const int wm = wid & 1, wn = wid >> 1;
    const int grp = lane >> 2, q = lane & 3;

    auto issue = [&](int st, int buf) {
        const int k0 = st * 64;
        for (int c = tid; c < 2048; c += 256) {
            int col8 = c & 7, row = (c >> 3) & 127, pl = c >> 10;
            const __nv_bfloat16* src = (pl ? Apl : Aph) + (size_t)(i0 + row) * 512 + k0 + col8 * 8;
            cp16(sb + buf * SA_BUF + pl * GA_PLB + (row * GA_STR + col8 * 8) * 2, src);
        }
        for (int c = tid; c < 1024; c += 256) {
            int col8 = c & 7, row = (c >> 3) & 63, pl = c >> 9;
            const __nv_bfloat16* src = (pl ? Wpl : Wph) + (size_t)(j0 + row) * 512 + k0 + col8 * 8;
            cp16(sb + SW_B + buf * SW_BUF + pl * GW_PLB + (row * GA_STR + col8 * 8) * 2, src);
        }
    };

    issue(0, 0); cp_commit();
    issue(1, 1); cp_commit();

    float acc[4][2][4];
#pragma unroll
    for (int a = 0; a < 4; a++)
#pragma unroll
        for (int b = 0; b < 2; b++)
#pragma unroll
            for (int c = 0; c < 4; c++) acc[a][b][c] = 0.f;

    for (int st = 0; st < 8; st++) {
        const int buf = st & 1;
        if (st == 7) cp_wait<0>(); else cp_wait<1>();
        __syncthreads();

        const char* Ab = gsm + buf * SA_BUF;
        const char* Wb = gsm + SW_B + buf * SW_BUF;
#pragma unroll
        for (int k16 = 0; k16 < 4; k16++) {
            const int ko = k16 * 16 + 2 * q;
            unsigned bh[2][2], bl[2][2];
#pragma unroll
            for (int nf = 0; nf < 2; nf++) {
                const int jl = wn * 16 + nf * 8 + grp;
                const char* wp = Wb + (jl * GA_STR + ko) * 2;
                bh[nf][0] = *(const unsigned*)wp;
                bh[nf][1] = *(const unsigned*)(wp + 16);
                bl[nf][0] = *(const unsigned*)(wp + GW_PLB);
                bl[nf][1] = *(const unsigned*)(wp + GW_PLB + 16);
            }
#pragma unroll
            for (int mf = 0; mf < 4; mf++) {
                const int row = wm * 64 + mf * 16 + grp;
                const char* ap = Ab + (row * GA_STR + ko) * 2;
                unsigned a0 = *(const unsigned*)ap;
                unsigned a1 = *(const unsigned*)(ap + 8 * GA_STR * 2);
                unsigned a2 = *(const unsigned*)(ap + 16);
                unsigned a3 = *(const unsigned*)(ap + 8 * GA_STR * 2 + 16);
                unsigned c0 = *(const unsigned*)(ap + GA_PLB);
                unsigned c1 = *(const unsigned*)(ap + GA_PLB + 8 * GA_STR * 2);
                unsigned c2 = *(const unsigned*)(ap + GA_PLB + 16);
                unsigned c3 = *(const unsigned*)(ap + GA_PLB + 8 * GA_STR * 2 + 16);
#pragma unroll
                for (int nf = 0; nf < 2; nf++) {
                    mma16816(acc[mf][nf][0], acc[mf][nf][1], acc[mf][nf][2], acc[mf][nf][3],
                             a0, a1, a2, a3, bh[nf][0], bh[nf][1]);
                    mma16816(acc[mf][nf][0], acc[mf][nf][1], acc[mf][nf][2], acc[mf][nf][3],
                             a0, a1, a2, a3, bl[nf][0], bl[nf][1]);
                    mma16816(acc[mf][nf][0], acc[mf][nf][1], acc[mf][nf][2], acc[mf][nf][3],
                             c0, c1, c2, c3, bh[nf][0], bh[nf][1]);
                }
            }
        }
        __syncthreads();
        if (st + 2 < 8) issue(st + 2, buf);
        cp_commit();
    }

#pragma unroll
    for (int mf = 0; mf < 4; mf++) {
#pragma unroll
        for (int nf = 0; nf < 2; nf++) {
#pragma unroll
            for (int half = 0; half < 2; half++) {
                const int i = i0 + wm * 64 + mf * 16 + grp + half * 8;
                const int j = j0 + wn * 16 + nf * 8 + 2 * q;
                float v0 = acc[mf][nf][half * 2]     + bias[j];
                float v1 = acc[mf][nf][half * 2 + 1] + bias[j + 1];
                if (DST == 3) {
                    *(float2*)&Cout[(size_t)i * 512 + j] = make_float2(v0, v1);
                    continue;
                }
                if (DST == 0) { v0 *= 0.125f; v1 *= 0.125f; }
                const int b = i >> 9, t = i & 511;
                const int hh = j >> 6, dh = j & 63;
                unsigned hi, lo;
                split2(v0, v1, hi, lo);
                if (DST == 0) {
                    size_t o = ((size_t)(b * NH_ + hh) * T_ + t) * 64 + dh;
                    *(unsigned*)&g_Qh[o] = hi; *(unsigned*)&g_Ql[o] = lo;
                } else if (DST == 1) {
                    size_t o = ((size_t)(b * NH_ + hh) * T_ + t) * 64 + dh;
                    *(unsigned*)&g_Kh[o] = hi; *(unsigned*)&g_Kl[o] = lo;
                } else {
                    __nv_bfloat16 h0 = __float2bfloat16(v0);
                    __nv_bfloat16 h1 = __float2bfloat16(v1);
                    size_t o = ((size_t)(b * NH_ + hh) * 64 + dh) * T_ + t;
                    g_VTh[o]       = h0;
                    g_VTh[o + T_]  = h1;
                    g_VTl[o]       = __float2bfloat16(v0 - __bfloat162float(h0));
                    g_VTl[o + T_]  = __float2bfloat16(v1 - __bfloat162float(h1));
                }
            }
        }
    }
}

// ---------------------------------------------------------------------------
// pos kernel (unchanged)
// ---------------------------------------------------------------------------
#define PR_STR 68
#define PTILE  (64 * PR_STR)

__global__ __launch_bounds__(128) void pos_kernel(const float* __restrict__ rel) {
    __shared__ float Rs[2 * PTILE];
    const int t = blockIdx.x, h = blockIdx.y;
    const int tid = threadIdx.x;
    const int wid = tid >> 5, lane = tid & 31;
    const int grp = lane >> 2, q = lane & 3;
    const unsigned sb = (unsigned)__cvta_generic_to_shared(Rs);

    unsigned Bh[4][2], Bl[4][2];
#pragma unroll
    for (int kk = 0; kk < 4; kk++) {
        size_t base = ((size_t)(grp*NH_+h)*T_ + t)*64 + kk*16 + 2*q;
        Bh[kk][0] = *(const unsigned*)&g_Qh[base];
        Bh[kk][1] = *(const unsigned*)&g_Qh[base + 8];
        Bl[kk][0] = *(const unsigned*)&g_Ql[base];
        Bl[kk][1] = *(const unsigned*)&g_Ql[base + 8];
    }

    auto issue = [&](int blk, int buf) {
        const float* base = rel + ((size_t)t*T_ + blk*64)*D_ + h*64;
#pragma unroll
        for (int p = 0; p < 8; p++) {
            int c = tid + p * 128;
            int row = c >> 4, col4 = c & 15;
            cp16(sb + (unsigned)(buf*PTILE + row*PR_STR + col4*4)*4,
                 base + (size_t)row*D_ + col4*4);
        }
    };

    issue(0, 0); cp_commit();
    issue(1, 1); cp_commit();

    for (int blk = 0; blk < 8; blk++) {
        const int buf = blk & 1;
        if (blk == 7) cp_wait<0>(); else cp_wait<1>();
        __syncthreads();

        const float* rs = Rs + buf*PTILE + (wid*16 + grp)*PR_STR;
        float c0 = 0.f, c1 = 0.f, c2 = 0.f, c3 = 0.f;
#pragma unroll
        for (int kk = 0; kk < 4; kk++) {
            float2 rA0 = *(const float2*)(rs + kk*16 + 2*q);
            float2 rA2 = *(const float2*)(rs + kk*16 + 2*q + 8);
            float2 rA1 = *(const float2*)(rs + 8*PR_STR + kk*16 + 2*q);
            float2 rA3 = *(const float2*)(rs + 8*PR_STR + kk*16 + 2*q + 8);
            unsigned ah0, al0, ah1, al1, ah2, al2, ah3, al3;
            split2(rA0.x, rA0.y, ah0, al0);
            split2(rA1.x, rA1.y, ah1, al1);
            split2(rA2.x, rA2.y, ah2, al2);
            split2(rA3.x, rA3.y, ah3, al3);
            mma16816(c0,c1,c2,c3, ah0,ah1,ah2,ah3, Bh[kk][0], Bh[kk][1]);
            mma16816(c0,c1,c2,c3, ah0,ah1,ah2,ah3, Bl[kk][0], Bl[kk][1]);
            mma16816(c0,c1,c2,c3, al0,al1,al2,al3, Bh[kk][0], Bh[kk][1]);
        }
        const int s0 = blk * 64 + wid * 16;
        size_t o = ((size_t)h*T_ + t) * B_;
        g_pos[(o + 2*q    )*T_ + s0 + grp    ] = c0;
        g_pos[(o + 2*q + 1)*T_ + s0 + grp    ] = c1;
        g_pos[(o + 2*q    )*T_ + s0 + grp + 8] = c2;
        g_pos[(o + 2*q + 1)*T_ + s0 + grp + 8] = c3;

        __syncthreads();
        if (blk + 2 < 8) issue(blk + 2, buf);
        cp_commit();
    }
}

// ---------------------------------------------------------------------------
// FA2 attention, t-tile 32, 512 threads: warp = (batch, mt-half).
// warps 0-7 -> mt=0 (t0..t0+15), warps 8-15 -> mt=1 (t0+16..t0+31), b = wid&7.
// ---------------------------------------------------------------------------
#define KS_B   0
#define KBUF_B 36864
#define KPL_B  18432
#define VS_B   73728
#define VBUF_B 49152
#define VPL_B  24576
#define PS_B   172032
#define PBUF_B 16384
#define SMEM_BYTES 204800

__global__ __launch_bounds__(512, 1) void attn_mma() {
    const int h  = blockIdx.y;
    const int t0 = blockIdx.x * 32;
    extern __shared__ char sm[];
    const unsigned sb = (unsigned)__cvta_generic_to_shared(sm);

    const int tid = threadIdx.x;
    const int wid = tid >> 5;
    const int lane = tid & 31;
    const int grp = lane >> 2, q = lane & 3;
    const int b = wid & 7, mt = wid >> 3;

    unsigned QAh[4][4], QAl[4][4];
#pragma unroll
    for (int kk = 0; kk < 4; kk++) {
        size_t base = ((size_t)(b*NH_+h)*T_ + t0 + mt*16 + grp)*64 + kk*16 + 2*q;
        QAh[kk][0] = *(const unsigned*)&g_Qh[base];
        QAh[kk][1] = *(const unsigned*)&g_Qh[base + 8*64];
        QAh[kk][2] = *(const unsigned*)&g_Qh[base + 8];
        QAh[kk][3] = *(const unsigned*)&g_Qh[base + 8*64 + 8];
        QAl[kk][0] = *(const unsigned*)&g_Ql[base];
        QAl[kk][1] = *(const unsigned*)&g_Ql[base + 8*64];
        QAl[kk][2] = *(const unsigned*)&g_Ql[base + 8];
        QAl[kk][3] = *(const unsigned*)&g_Ql[base + 8*64 + 8];
    }

    auto issue_tile = [&](int s0, int buf) {
        for (int i = tid; i < 2048; i += 512) {            // K
            int q4 = i & 7, row = i >> 3;
            int s = row & 15, bb = (row >> 4) & 7, pl = row >> 7;
            const __nv_bfloat16* src =
                (pl ? g_Kl : g_Kh) + ((size_t)(bb*NH_+h)*T_ + s0 + s)*64 + q4*8;
            cp16(sb + KS_B + buf*KBUF_B + pl*KPL_B + (bb*16 + s)*144 + q4*16, src);
        }
        for (int i = tid; i < 2048; i += 512) {            // V^T
            int q4 = i & 1, row = i >> 1;
            int d = row & 63, bb = (row >> 6) & 7, pl = row >> 9;
            const __nv_bfloat16* src =
                (pl ? g_VTl : g_VTh) + ((size_t)(bb*NH_+h)*64 + d)*T_ + s0 + q4*8;
            cp16(sb + VS_B + buf*VBUF_B + pl*VPL_B + (bb*64 + d)*48 + q4*16, src);
        }
        for (int i = tid; i < 1024; i += 512) {            // pos bias
            int q4 = i & 3, row = i >> 2;
            int t = row & 31, bb = row >> 5;
            const float* src = g_pos + ((size_t)(h*T_ + t0 + t)*B_ + bb)*T_ + s0 + q4*4;
            cp16(sb + PS_B + buf*PBUF_B + (bb*32 + t)*64 + q4*16, src);
        }
    };

    issue_tile(0, 0);  cp_commit();
    issue_tile(16, 1); cp_commit();

    float ctx[8][4];
#pragma unroll
    for (int nt = 0; nt < 8; nt++)
#pragma unroll
        for (int i = 0; i < 4; i++) ctx[nt][i] = 0.f;
    float m_a = -1e30f, m_b = -1e30f, l_a = 0.f, l_b = 0.f;

    for (int it = 0; it < 32; it++) {
        const int buf = it & 1;
        if (it == 31) cp_wait<0>(); else cp_wait<1>();
        __syncthreads();

        float sg[2][4];
        const float* pp = (const float*)(sm + PS_B + buf*PBUF_B) + (b*32 + mt*16 + grp)*16;
#pragma unroll
        for (int ng = 0; ng < 2; ng++) {
            float2 pa = *(const float2*)(pp + ng*8 + 2*q);
            float2 pb = *(const float2*)(pp + 8*16 + ng*8 + 2*q);
            float c0 = pa.x, c1 = pa.y, c2 = pb.x, c3 = pb.y;
#pragma unroll
            for (int kk = 0; kk < 4; kk++) {
                const char* kp = sm + KS_B + buf*KBUF_B + (b*16 + ng*8 + grp)*144 + kk*32 + q*4;
                unsigned bh0 = *(const unsigned*)kp;
                unsigned bh1 = *(const unsigned*)(kp + 16);
                unsigned bl0 = *(const unsigned*)(kp + KPL_B);
                unsigned bl1 = *(const unsigned*)(kp + KPL_B + 16);
                mma16816(c0,c1,c2,c3, QAh[kk][0],QAh[kk][1],QAh[kk][2],QAh[kk][3], bh0, bh1);
                mma16816(c0,c1,c2,c3, QAh[kk][0],QAh[kk][1],QAh[kk][2],QAh[kk][3], bl0, bl1);
                mma16816(c0,c1,c2,c3, QAl[kk][0],QAl[kk][1],QAl[kk][2],QAl[kk][3], bh0, bh1);
            }
            sg[ng][0] = c0; sg[ng][1] = c1; sg[ng][2] = c2; sg[ng][3] = c3;
        }

        float ma = fmaxf(fmaxf(sg[0][0], sg[0][1]), fmaxf(sg[1][0], sg[1][1]));
        float mb = fmaxf(fmaxf(sg[0][2], sg[0][3]), fmaxf(sg[1][2], sg[1][3]));
        ma = fmaxf(ma, __shfl_xor_sync(0xffffffffu, ma, 1, 4));
        ma = fmaxf(ma, __shfl_xor_sync(0xffffffffu, ma, 2, 4));
        mb = fmaxf(mb, __shfl_xor_sync(0xffffffffu, mb, 1, 4));
        mb = fmaxf(mb, __shfl_xor_sync(0xffffffffu, mb, 2, 4));
        float mna = fmaxf(m_a, ma), mnb = fmaxf(m_b, mb);
        float sca = __expf(m_a - mna), scb = __expf(m_b - mnb);
        float pa0 = __expf(sg[0][0] - mna), pa1 = __expf(sg[0][1] - mna);
        float pa2 = __expf(sg[1][0] - mna), pa3 = __expf(sg[1][1] - mna);
        float pb0 = __expf(sg[0][2] - mnb), pb1 = __expf(sg[0][3] - mnb);
        float pb2 = __expf(sg[1][2] - mnb), pb3 = __expf(sg[1][3] - mnb);
        float la = pa0 + pa1 + pa2 + pa3;
        float lb = pb0 + pb1 + pb2 + pb3;
        la += __shfl_xor_sync(0xffffffffu, la, 1, 4);
        la += __shfl_xor_sync(0xffffffffu, la, 2, 4);
        lb += __shfl_xor_sync(0xffffffffu, lb, 1, 4);
        lb += __shfl_xor_sync(0xffffffffu, lb, 2, 4);
        l_a = l_a * sca + la; l_b = l_b * scb + lb;
        m_a = mna; m_b = mnb;

        unsigned ah0, al0, ah1, al1, ah2, al2, ah3, al3;
        split2(pa0, pa1, ah0, al0);
        split2(pb0, pb1, ah1, al1);
        split2(pa2, pa3, ah2, al2);
        split2(pb2, pb3, ah3, al3);

#pragma unroll
        for (int nt = 0; nt < 8; nt++) {
            ctx[nt][0] *= sca; ctx[nt][1] *= sca;
            ctx[nt][2] *= scb; ctx[nt][3] *= scb;
        }
#pragma unroll
        for (int nt = 0; nt < 8; nt++) {
            const char* vp = sm + VS_B + buf*VBUF_B + (b*64 + nt*8 + grp)*48 + q*4;
            unsigned bh0 = *(const unsigned*)vp;
            unsigned bh1 = *(const unsigned*)(vp + 16);
            unsigned bl0 = *(const unsigned*)(vp + VPL_B);
            unsigned bl1 = *(const unsigned*)(vp + VPL_B + 16);
            mma16816(ctx[nt][0],ctx[nt][1],ctx[nt][2],ctx[nt][3], ah0,ah1,ah2,ah3, bh0, bh1);
            mma16816(ctx[nt][0],ctx[nt][1],ctx[nt][2],ctx[nt][3], al0,al1,al2,al3, bh0, bh1);
            mma16816(ctx[nt][0],ctx[nt][1],ctx[nt][2],ctx[nt][3], ah0,ah1,ah2,ah3, bl0, bl1);
        }

        __syncthreads();
        if (it + 2 < 32) issue_tile((it + 2) * 16, buf);
        cp_commit();
    }

    const float inva = 1.0f / l_a, invb = 1.0f / l_b;
    size_t r0 = ((size_t)b*T_ + t0 + mt*16 + grp)*512 + h*64 + 2*q;
    size_t r1 = r0 + 8 * 512;
#pragma unroll
    for (int nt = 0; nt < 8; nt++) {
        unsigned hi, lo;
        split2(ctx[nt][0]*inva, ctx[nt][1]*inva, hi, lo);
        *(unsigned*)&g_CXh[r0 + nt*8] = hi;
        *(unsigned*)&g_CXl[r0 + nt*8] = lo;
        split2(ctx[nt][2]*invb, ctx[nt][3]*invb, hi, lo);
        *(unsigned*)&g_CXh[r1 + nt*8] = hi;
        *(unsigned*)&g_CXl[r1 + nt*8] = lo;
    }
}

// ---------------------------------------------------------------------------
extern "C" void kernel_launch(void* const* d_in, const int* in_sizes, int n_in,
                              void* d_out, int out_size) {
    const float* x   = (const float*)d_in[0];
    const float* rel = (const float*)d_in[1];
    const float* Wq  = (const float*)d_in[2];
    const float* bq  = (const float*)d_in[3];
    const float* Wk  = (const float*)d_in[4];
    const float* bk  = (const float*)d_in[5];
    const float* Wv  = (const float*)d_in[6];
    const float* bv  = (const float*)d_in[7];
    const float* Wo  = (const float*)d_in[8];
    const float* bo  = (const float*)d_in[9];
    float* out = (float*)d_out;

    cudaFuncSetAttribute(attn_mma, cudaFuncAttributeMaxDynamicSharedMemorySize, SMEM_BYTES);
    cudaFuncSetAttribute(mma_gemm2<0>, cudaFuncAttributeMaxDynamicSharedMemorySize, GSM_BYTES);
    cudaFuncSetAttribute(mma_gemm2<1>, cudaFuncAttributeMaxDynamicSharedMemorySize, GSM_BYTES);
    cudaFuncSetAttribute(mma_gemm2<2>, cudaFuncAttributeMaxDynamicSharedMemorySize, GSM_BYTES);
    cudaFuncSetAttribute(mma_gemm2<3>, cudaFuncAttributeMaxDynamicSharedMemorySize, GSM_BYTES);

    split_kernel<<<dim3(256, 5), 256>>>(x, Wq, Wk, Wv, Wo);

    dim3 gg(32, 8);
    mma_gemm2<0><<<gg, 256, GSM_BYTES>>>(bq, nullptr);
    mma_gemm2<1><<<gg, 256, GSM_BYTES>>>(bk, nullptr);
    mma_gemm2<2><<<gg, 256, GSM_BYTES>>>(bv, nullptr);

    pos_kernel<<<dim3(T_, NH_), 128>>>(rel);

    attn_mma<<<dim3(T_ / 32, NH_), 512, SMEM_BYTES>>>();

    mma_gemm2<3><<<gg, 256, GSM_BYTES>>>(bo, out);
}

// round 14
// speedup vs baseline: 1.3488x; 1.0424x over previous
#include <cuda_runtime.h>
#include <cuda_bf16.h>
#include <cstdint>
#include <math.h>

#define B_   8
#define T_   512
#define D_   512
#define NH_  8
#define DH_  64

#define PLANE_ELEMS (B_ * NH_ * T_ * DH_)
__device__ __nv_bfloat16 g_Qh[PLANE_ELEMS], g_Ql[PLANE_ELEMS];   // [b][h][t][d], pre-scaled 1/8
__device__ __nv_bfloat16 g_Kh[PLANE_ELEMS], g_Kl[PLANE_ELEMS];   // [b][h][t][d]
__device__ __nv_bfloat16 g_VTh[PLANE_ELEMS], g_VTl[PLANE_ELEMS]; // [b][h][d][t]
__device__ float g_pos[NH_ * T_ * B_ * T_];                      // [h][t][b][s]

__device__ __nv_bfloat16 g_Xh[4096 * 512], g_Xl[4096 * 512];
__device__ __nv_bfloat16 g_CXh[4096 * 512], g_CXl[4096 * 512];
__device__ __nv_bfloat16 g_Wqh[512 * 512], g_Wql[512 * 512];
__device__ __nv_bfloat16 g_Wkh[512 * 512], g_Wkl[512 * 512];
__device__ __nv_bfloat16 g_Wvh[512 * 512], g_Wvl[512 * 512];
__device__ __nv_bfloat16 g_Woh[512 * 512], g_Wol[512 * 512];

__device__ __forceinline__ void cp16(unsigned smem_addr, const void* g) {
    asm volatile("cp.async.cg.shared.global [%0], [%1], 16;\n" :: "r"(smem_addr), "l"(g));
}
__device__ __forceinline__ void cp_commit() { asm volatile("cp.async.commit_group;\n"); }
template <int N> __device__ __forceinline__ void cp_wait() {
    asm volatile("cp.async.wait_group %0;\n" :: "n"(N));
}
__device__ __forceinline__ unsigned pack2(__nv_bfloat16 x, __nv_bfloat16 y) {
    __nv_bfloat162 t; t.x = x; t.y = y;
    return *reinterpret_cast<unsigned*>(&t);
}
__device__ __forceinline__ void split2(float x, float y, unsigned& hi, unsigned& lo) {
    __nv_bfloat16 xh = __float2bfloat16(x), yh = __float2bfloat16(y);
    hi = pack2(xh, yh);
    lo = pack2(__float2bfloat16(x - __bfloat162float(xh)),
               __float2bfloat16(y - __bfloat162float(yh)));
}
__device__ __forceinline__ void mma16816(float& c0, float& c1, float& c2, float& c3,
                                         unsigned a0, unsigned a1, unsigned a2, unsigned a3,
                                         unsigned b0, unsigned b1) {
    asm volatile("mma.sync.aligned.m16n8k16.row.col.f32.bf16.bf16.f32 "
                 "{%0,%1,%2,%3},{%4,%5,%6,%7},{%8,%9},{%0,%1,%2,%3};\n"
                 : "+f"(c0), "+f"(c1), "+f"(c2), "+f"(c3)
                 : "r"(a0), "r"(a1), "r"(a2), "r"(a3), "r"(b0), "r"(b1));
}

// ---------------------------------------------------------------------------
// split x + 4 weights into bf16 hi/lo planes (once)
// ---------------------------------------------------------------------------
__global__ __launch_bounds__(256) void split_kernel(const float* __restrict__ x,
                                                    const float* __restrict__ Wq,
                                                    const float* __restrict__ Wk,
                                                    const float* __restrict__ Wv,
                                                    const float* __restrict__ Wo) {
    const int seg = blockIdx.y;
    const float* src;
    __nv_bfloat16 *dh, *dl;
    int n;
    if (seg == 0)      { src = x;  dh = g_Xh;  dl = g_Xl;  n = 4096 * 512 / 2; }
    else if (seg == 1) { src = Wq; dh = g_Wqh; dl = g_Wql; n = 512 * 512 / 2; }
    else if (seg == 2) { src = Wk; dh = g_Wkh; dl = g_Wkl; n = 512 * 512 / 2; }
    else if (seg == 3) { src = Wv; dh = g_Wvh; dl = g_Wvl; n = 512 * 512 / 2; }
    else               { src = Wo; dh = g_Woh; dl = g_Wol; n = 512 * 512 / 2; }
    for (int i = blockIdx.x * 256 + threadIdx.x; i < n; i += gridDim.x * 256) {
        float2 v = ((const float2*)src)[i];
        unsigned hi, lo;
        split2(v.x, v.y, hi, lo);
        ((unsigned*)dh)[i] = hi;
        ((unsigned*)dl)[i] = lo;
    }
}

// ---------------------------------------------------------------------------
// bf16-plane GEMM (R10-proven version; scalar fragment loads)
// ---------------------------------------------------------------------------
#define GA_STR 72
#define GA_PLB (128 * GA_STR * 2)
#define SA_BUF (2 * GA_PLB)
#define GW_PLB (64 * GA_STR * 2)
#define SW_BUF (2 * GW_PLB)
#define SW_B   (2 * SA_BUF)
#define GSM_BYTES (SW_B + 2 * SW_BUF)

template <int DST>
__global__ __launch_bounds__(256) void mma_gemm2(const float* __restrict__ bias,
                                                 float* __restrict__ Cout) {
    extern __shared__ char gsm[];
    const unsigned sb = (unsigned)__cvta_generic_to_shared(gsm);

    const __nv_bfloat16 *Aph, *Apl, *Wph, *Wpl;
    if (DST == 3) { Aph = g_CXh; Apl = g_CXl; } else { Aph = g_Xh; Apl = g_Xl; }
    if (DST == 0)      { Wph = g_Wqh; Wpl = g_Wql; }
    else if (DST == 1) { Wph = g_Wkh; Wpl = g_Wkl; }
    else if (DST == 2) { Wph = g_Wvh; Wpl = g_Wvl; }
    else               { Wph = g_Woh; Wpl = g_Wol; }

    const int i0 = blockIdx.x * 128, j0 = blockIdx.y * 64;
    const int tid = threadIdx.x;
    const int wid = tid >> 5, lane = tid & 31;
    const int wm = wid & 1, wn = wid >> 1;
    const int grp = lane >> 2, q = lane & 3;

    auto issue = [&](int st, int buf) {
        const int k0 = st * 64;
        for (int c = tid; c < 2048; c += 256) {
            int col8 = c & 7, row = (c >> 3) & 127, pl = c >> 10;
            const __nv_bfloat16* src = (pl ? Apl : Aph) + (size_t)(i0 + row) * 512 + k0 + col8 * 8;
            cp16(sb + buf * SA_BUF + pl * GA_PLB + (row * GA_STR + col8 * 8) * 2, src);
        }
        for (int c = tid; c < 1024; c += 256) {
            int col8 = c & 7, row = (c >> 3) & 63, pl = c >> 9;
            const __nv_bfloat16* src = (pl ? Wpl : Wph) + (size_t)(j0 + row) * 512 + k0 + col8 * 8;
            cp16(sb + SW_B + buf * SW_BUF + pl * GW_PLB + (row * GA_STR + col8 * 8) * 2, src);
        }
    };

    issue(0, 0); cp_commit();
    issue(1, 1); cp_commit();

    float acc[4][2][4];
#pragma unroll
    for (int a = 0; a < 4; a++)
#pragma unroll
        for (int b = 0; b < 2; b++)
#pragma unroll
            for (int c = 0; c < 4; c++) acc[a][b][c] = 0.f;

    for (int st = 0; st < 8; st++) {
        const int buf = st & 1;
        if (st == 7) cp_wait<0>(); else cp_wait<1>();
        __syncthreads();

        const char* Ab = gsm + buf * SA_BUF;
        const char* Wb = gsm + SW_B + buf * SW_BUF;
#pragma unroll
        for (int k16 = 0; k16 < 4; k16++) {
            const int ko = k16 * 16 + 2 * q;
            unsigned bh[2][2], bl[2][2];
#pragma unroll
            for (int nf = 0; nf < 2; nf++) {
                const int jl = wn * 16 + nf * 8 + grp;
                const char* wp = Wb + (jl * GA_STR + ko) * 2;
                bh[nf][0] = *(const unsigned*)wp;
                bh[nf][1] = *(const unsigned*)(wp + 16);
                bl[nf][0] = *(const unsigned*)(wp + GW_PLB);
                bl[nf][1] = *(const unsigned*)(wp + GW_PLB + 16);
            }
#pragma unroll
            for (int mf = 0; mf < 4; mf++) {
                const int row = wm * 64 + mf * 16 + grp;
                const char* ap = Ab + (row * GA_STR + ko) * 2;
                unsigned a0 = *(const unsigned*)ap;
                unsigned a1 = *(const unsigned*)(ap + 8 * GA_STR * 2);
                unsigned a2 = *(const unsigned*)(ap + 16);
                unsigned a3 = *(const unsigned*)(ap + 8 * GA_STR * 2 + 16);
                unsigned c0 = *(const unsigned*)(ap + GA_PLB);
                unsigned c1 = *(const unsigned*)(ap + GA_PLB + 8 * GA_STR * 2);
                unsigned c2 = *(const unsigned*)(ap + GA_PLB + 16);
                unsigned c3 = *(const unsigned*)(ap + GA_PLB + 8 * GA_STR * 2 + 16);
#pragma unroll
                for (int nf = 0; nf < 2; nf++) {
                    mma16816(acc[mf][nf][0], acc[mf][nf][1], acc[mf][nf][2], acc[mf][nf][3],
                             a0, a1, a2, a3, bh[nf][0], bh[nf][1]);
                    mma16816(acc[mf][nf][0], acc[mf][nf][1], acc[mf][nf][2], acc[mf][nf][3],
                             a0, a1, a2, a3, bl[nf][0], bl[nf][1]);
                    mma16816(acc[mf][nf][0], acc[mf][nf][1], acc[mf][nf][2], acc[mf][nf][3],
                             c0, c1, c2, c3, bh[nf][0], bh[nf][1]);
                }
            }
        }
        __syncthreads();
        if (st + 2 < 8) issue(st + 2, buf);
        cp_commit();
    }

#pragma unroll
    for (int mf = 0; mf < 4; mf++) {
#pragma unroll
        for (int nf = 0; nf < 2; nf++) {
#pragma unroll
            for (int half = 0; half < 2; half++) {
                const int i = i0 + wm * 64 + mf * 16 + grp + half * 8;
                const int j = j0 + wn * 16 + nf * 8 + 2 * q;
                float v0 = acc[mf][nf][half * 2]     + bias[j];
                float v1 = acc[mf][nf][half * 2 + 1] + bias[j + 1];
                if (DST == 3) {
                    *(float2*)&Cout[(size_t)i * 512 + j] = make_float2(v0, v1);
                    continue;
                }
                if (DST == 0) { v0 *= 0.125f; v1 *= 0.125f; }
                const int b = i >> 9, t = i & 511;
                const int hh = j >> 6, dh = j & 63;
                unsigned hi, lo;
                split2(v0, v1, hi, lo);
                if (DST == 0) {
                    size_t o = ((size_t)(b * NH_ + hh) * T_ + t) * 64 + dh;
                    *(unsigned*)&g_Qh[o] = hi; *(unsigned*)&g_Ql[o] = lo;
                } else if (DST == 1) {
                    size_t o = ((size_t)(b * NH_ + hh) * T_ + t) * 64 + dh;
                    *(unsigned*)&g_Kh[o] = hi; *(unsigned*)&g_Kl[o] = lo;
                } else {
                    __nv_bfloat16 h0 = __float2bfloat16(v0);
                    __nv_bfloat16 h1 = __float2bfloat16(v1);
                    size_t o = ((size_t)(b * NH_ + hh) * 64 + dh) * T_ + t;
                    g_VTh[o]       = h0;
                    g_VTh[o + T_]  = h1;
                    g_VTl[o]       = __float2bfloat16(v0 - __bfloat162float(h0));
                    g_VTl[o + T_]  = __float2bfloat16(v1 - __bfloat162float(h1));
                }
            }
        }
    }
}

// ---------------------------------------------------------------------------
// pos kernel (unchanged)
// ---------------------------------------------------------------------------
#define PR_STR 68
#define PTILE  (64 * PR_STR)

__global__ __launch_bounds__(128) void pos_kernel(const float* __restrict__ rel) {
    __shared__ float Rs[2 * PTILE];
    const int t = blockIdx.x, h = blockIdx.y;
    const int tid = threadIdx.x;
    const int wid = tid >> 5, lane = tid & 31;
    const int grp = lane >> 2, q = lane & 3;
    const unsigned sb = (unsigned)__cvta_generic_to_shared(Rs);

    unsigned Bh[4][2], Bl[4][2];
#pragma unroll
    for (int kk = 0; kk < 4; kk++) {
        size_t base = ((size_t)(grp*NH_+h)*T_ + t)*64 + kk*16 + 2*q;
        Bh[kk][0] = *(const unsigned*)&g_Qh[base];
        Bh[kk][1] = *(const unsigned*)&g_Qh[base + 8];
        Bl[kk][0] = *(const unsigned*)&g_Ql[base];
        Bl[kk][1] = *(const unsigned*)&g_Ql[base + 8];
    }

    auto issue = [&](int blk, int buf) {
        const float* base = rel + ((size_t)t*T_ + blk*64)*D_ + h*64;
#pragma unroll
        for (int p = 0; p < 8; p++) {
            int c = tid + p * 128;
            int row = c >> 4, col4 = c & 15;
            cp16(sb + (unsigned)(buf*PTILE + row*PR_STR + col4*4)*4,
                 base + (size_t)row*D_ + col4*4);
        }
    };

    issue(0, 0); cp_commit();
    issue(1, 1); cp_commit();

    for (int blk = 0; blk < 8; blk++) {
        const int buf = blk & 1;
        if (blk == 7) cp_wait<0>(); else cp_wait<1>();
        __syncthreads();

        const float* rs = Rs + buf*PTILE + (wid*16 + grp)*PR_STR;
        float c0 = 0.f, c1 = 0.f, c2 = 0.f, c3 = 0.f;
#pragma unroll
        for (int kk = 0; kk < 4; kk++) {
            float2 rA0 = *(const float2*)(rs + kk*16 + 2*q);
            float2 rA2 = *(const float2*)(rs + kk*16 + 2*q + 8);
            float2 rA1 = *(const float2*)(rs + 8*PR_STR + kk*16 + 2*q);
            float2 rA3 = *(const float2*)(rs + 8*PR_STR + kk*16 + 2*q + 8);
            unsigned ah0, al0, ah1, al1, ah2, al2, ah3, al3;
            split2(rA0.x, rA0.y, ah0, al0);
            split2(rA1.x, rA1.y, ah1, al1);
            split2(rA2.x, rA2.y, ah2, al2);
            split2(rA3.x, rA3.y, ah3, al3);
            mma16816(c0,c1,c2,c3, ah0,ah1,ah2,ah3, Bh[kk][0], Bh[kk][1]);
            mma16816(c0,c1,c2,c3, ah0,ah1,ah2,ah3, Bl[kk][0], Bl[kk][1]);
            mma16816(c0,c1,c2,c3, al0,al1,al2,al3, Bh[kk][0], Bh[kk][1]);
        }
        const int s0 = blk * 64 + wid * 16;
        size_t o = ((size_t)h*T_ + t) * B_;
        g_pos[(o + 2*q    )*T_ + s0 + grp    ] = c0;
        g_pos[(o + 2*q + 1)*T_ + s0 + grp    ] = c1;
        g_pos[(o + 2*q    )*T_ + s0 + grp + 8] = c2;
        g_pos[(o + 2*q + 1)*T_ + s0 + grp + 8] = c3;

        __syncthreads();
        if (blk + 2 < 8) issue(blk + 2, buf);
        cp_commit();
    }
}

// ---------------------------------------------------------------------------
// FA2 attention, batch-split CTAs: CTA = (t-tile 32, h, b-group of 4).
// 256 threads, warp = (b4 = wid&3, mt = wid>>2). 2 CTAs/SM, grid 16x8x2.
// ---------------------------------------------------------------------------
#define KS_B   0
#define KBUF_B 18432
#define KPL_B  9216
#define VS_B   36864
#define VBUF_B 24576
#define VPL_B  12288
#define PS_B   86016
#define PBUF_B 8192
#define SMEM_BYTES 102400

__global__ __launch_bounds__(256, 2) void attn_mma() {
    const int h  = blockIdx.y;
    const int t0 = blockIdx.x * 32;
    const int bg = blockIdx.z;           // batch group: batches bg*4 .. bg*4+3
    extern __shared__ char sm[];
    const unsigned sb = (unsigned)__cvta_generic_to_shared(sm);

    const int tid = threadIdx.x;
    const int wid = tid >> 5;
    const int lane = tid & 31;
    const int grp = lane >> 2, q = lane & 3;
    const int b4 = wid & 3, mt = wid >> 2;
    const int b = bg * 4 + b4;           // global batch

    unsigned QAh[4][4], QAl[4][4];
#pragma unroll
    for (int kk = 0; kk < 4; kk++) {
        size_t base = ((size_t)(b*NH_+h)*T_ + t0 + mt*16 + grp)*64 + kk*16 + 2*q;
        QAh[kk][0] = *(const unsigned*)&g_Qh[base];
        QAh[kk][1] = *(const unsigned*)&g_Qh[base + 8*64];
        QAh[kk][2] = *(const unsigned*)&g_Qh[base + 8];
        QAh[kk][3] = *(const unsigned*)&g_Qh[base + 8*64 + 8];
        QAl[kk][0] = *(const unsigned*)&g_Ql[base];
        QAl[kk][1] = *(const unsigned*)&g_Ql[base + 8*64];
        QAl[kk][2] = *(const unsigned*)&g_Ql[base + 8];
        QAl[kk][3] = *(const unsigned*)&g_Ql[base + 8*64 + 8];
    }

    auto issue_tile = [&](int s0, int buf) {
        for (int i = tid; i < 1024; i += 256) {            // K: 4b x 16s x 8q4 x 2pl
            int q4 = i & 7, row = i >> 3;
            int s = row & 15, bb = (row >> 4) & 3, pl = row >> 6;
            const __nv_bfloat16* src =
                (pl ? g_Kl : g_Kh) + ((size_t)((bg*4+bb)*NH_+h)*T_ + s0 + s)*64 + q4*8;
            cp16(sb + KS_B + buf*KBUF_B + pl*KPL_B + (bb*16 + s)*144 + q4*16, src);
        }
        for (int i = tid; i < 1024; i += 256) {            // V^T: 4b x 64d x 2q4 x 2pl
            int q4 = i & 1, row = i >> 1;
            int d = row & 63, bb = (row >> 6) & 3, pl = row >> 8;
            const __nv_bfloat16* src =
                (pl ? g_VTl : g_VTh) + ((size_t)((bg*4+bb)*NH_+h)*64 + d)*T_ + s0 + q4*8;
            cp16(sb + VS_B + buf*VBUF_B + pl*VPL_B + (bb*64 + d)*48 + q4*16, src);
        }
        for (int i = tid; i < 512; i += 256) {             // pos: 4b x 32t x 4q4
            int q4 = i & 3, row = i >> 2;
            int t = row & 31, bb = row >> 5;
            const float* src = g_pos + ((size_t)(h*T_ + t0 + t)*B_ + bg*4 + bb)*T_ + s0 + q4*4;
            cp16(sb + PS_B + buf*PBUF_B + (bb*32 + t)*64 + q4*16, src);
        }
    };

    issue_tile(0, 0);  cp_commit();
    issue_tile(16, 1); cp_commit();

    float ctx[8][4];
#pragma unroll
    for (int nt = 0; nt < 8; nt++)
#pragma unroll
        for (int i = 0; i < 4; i++) ctx[nt][i] = 0.f;
    float m_a = -1e30f, m_b = -1e30f, l_a = 0.f, l_b = 0.f;

    for (int it = 0; it < 32; it++) {
        const int buf = it & 1;
        if (it == 31) cp_wait<0>(); else cp_wait<1>();
        __syncthreads();

        float sg[2][4];
        const float* pp = (const float*)(sm + PS_B + buf*PBUF_B) + (b4*32 + mt*16 + grp)*16;
#pragma unroll
        for (int ng = 0; ng < 2; ng++) {
            float2 pa = *(const float2*)(pp + ng*8 + 2*q);
            float2 pb = *(const float2*)(pp + 8*16 + ng*8 + 2*q);
            float c0 = pa.x, c1 = pa.y, c2 = pb.x, c3 = pb.y;
#pragma unroll
            for (int kk = 0; kk < 4; kk++) {
                const char* kp = sm + KS_B + buf*KBUF_B + (b4*16 + ng*8 + grp)*144 + kk*32 + q*4;
                unsigned bh0 = *(const unsigned*)kp;
                unsigned bh1 = *(const unsigned*)(kp + 16);
                unsigned bl0 = *(const unsigned*)(kp + KPL_B);
                unsigned bl1 = *(const unsigned*)(kp + KPL_B + 16);
                mma16816(c0,c1,c2,c3, QAh[kk][0],QAh[kk][1],QAh[kk][2],QAh[kk][3], bh0, bh1);
                mma16816(c0,c1,c2,c3, QAh[kk][0],QAh[kk][1],QAh[kk][2],QAh[kk][3], bl0, bl1);
                mma16816(c0,c1,c2,c3, QAl[kk][0],QAl[kk][1],QAl[kk][2],QAl[kk][3], bh0, bh1);
            }
            sg[ng][0] = c0; sg[ng][1] = c1; sg[ng][2] = c2; sg[ng][3] = c3;
        }

        float ma = fmaxf(fmaxf(sg[0][0], sg[0][1]), fmaxf(sg[1][0], sg[1][1]));
        float mb = fmaxf(fmaxf(sg[0][2], sg[0][3]), fmaxf(sg[1][2], sg[1][3]));
        ma = fmaxf(ma, __shfl_xor_sync(0xffffffffu, ma, 1, 4));
        ma = fmaxf(ma, __shfl_xor_sync(0xffffffffu, ma, 2, 4));
        mb = fmaxf(mb, __shfl_xor_sync(0xffffffffu, mb, 1, 4));
        mb = fmaxf(mb, __shfl_xor_sync(0xffffffffu, mb, 2, 4));
        float mna = fmaxf(m_a, ma), mnb = fmaxf(m_b, mb);
        float sca = __expf(m_a - mna), scb = __expf(m_b - mnb);
        float pa0 = __expf(sg[0][0] - mna), pa1 = __expf(sg[0][1] - mna);
        float pa2 = __expf(sg[1][0] - mna), pa3 = __expf(sg[1][1] - mna);
        float pb0 = __expf(sg[0][2] - mnb), pb1 = __expf(sg[0][3] - mnb);
        float pb2 = __expf(sg[1][2] - mnb), pb3 = __expf(sg[1][3] - mnb);
        float la = pa0 + pa1 + pa2 + pa3;
        float lb = pb0 + pb1 + pb2 + pb3;
        la += __shfl_xor_sync(0xffffffffu, la, 1, 4);
        la += __shfl_xor_sync(0xffffffffu, la, 2, 4);
        lb += __shfl_xor_sync(0xffffffffu, lb, 1, 4);
        lb += __shfl_xor_sync(0xffffffffu, lb, 2, 4);
        l_a = l_a * sca + la; l_b = l_b * scb + lb;
        m_a = mna; m_b = mnb;

        unsigned ah0, al0, ah1, al1, ah2, al2, ah3, al3;
        split2(pa0, pa1, ah0, al0);
        split2(pb0, pb1, ah1, al1);
        split2(pa2, pa3, ah2, al2);
        split2(pb2, pb3, ah3, al3);

#pragma unroll
        for (int nt = 0; nt < 8; nt++) {
            ctx[nt][0] *= sca; ctx[nt][1] *= sca;
            ctx[nt][2] *= scb; ctx[nt][3] *= scb;
        }
#pragma unroll
        for (int nt = 0; nt < 8; nt++) {
            const char* vp = sm + VS_B + buf*VBUF_B + (b4*64 + nt*8 + grp)*48 + q*4;
            unsigned bh0 = *(const unsigned*)vp;
            unsigned bh1 = *(const unsigned*)(vp + 16);
            unsigned bl0 = *(const unsigned*)(vp + VPL_B);
            unsigned bl1 = *(const unsigned*)(vp + VPL_B + 16);
            mma16816(ctx[nt][0],ctx[nt][1],ctx[nt][2],ctx[nt][3], ah0,ah1,ah2,ah3, bh0, bh1);
            mma16816(ctx[nt][0],ctx[nt][1],ctx[nt][2],ctx[nt][3], al0,al1,al2,al3, bh0, bh1);
            mma16816(ctx[nt][0],ctx[nt][1],ctx[nt][2],ctx[nt][3], ah0,ah1,ah2,ah3, bl0, bl1);
        }

        __syncthreads();
        if (it + 2 < 32) issue_tile((it + 2) * 16, buf);
        cp_commit();
    }

    const float inva = 1.0f / l_a, invb = 1.0f / l_b;
    size_t r0 = ((size_t)b*T_ + t0 + mt*16 + grp)*512 + h*64 + 2*q;
    size_t r1 = r0 + 8 * 512;
#pragma unroll
    for (int nt = 0; nt < 8; nt++) {
        unsigned hi, lo;
        split2(ctx[nt][0]*inva, ctx[nt][1]*inva, hi, lo);
        *(unsigned*)&g_CXh[r0 + nt*8] = hi;
        *(unsigned*)&g_CXl[r0 + nt*8] = lo;
        split2(ctx[nt][2]*invb, ctx[nt][3]*invb, hi, lo);
        *(unsigned*)&g_CXh[r1 + nt*8] = hi;
        *(unsigned*)&g_CXl[r1 + nt*8] = lo;
    }
}

// ---------------------------------------------------------------------------
extern "C" void kernel_launch(void* const* d_in, const int* in_sizes, int n_in,
                              void* d_out, int out_size) {
    const float* x   = (const float*)d_in[0];
    const float* rel = (const float*)d_in[1];
    const float* Wq  = (const float*)d_in[2];
    const float* bq  = (const float*)d_in[3];
    const float* Wk  = (const float*)d_in[4];
    const float* bk  = (const float*)d_in[5];
    const float* Wv  = (const float*)d_in[6];
    const float* bv  = (const float*)d_in[7];
    const float* Wo  = (const float*)d_in[8];
    const float* bo  = (const float*)d_in[9];
    float* out = (float*)d_out;

    cudaFuncSetAttribute(attn_mma, cudaFuncAttributeMaxDynamicSharedMemorySize, SMEM_BYTES);
    cudaFuncSetAttribute(mma_gemm2<0>, cudaFuncAttributeMaxDynamicSharedMemorySize, GSM_BYTES);
    cudaFuncSetAttribute(mma_gemm2<1>, cudaFuncAttributeMaxDynamicSharedMemorySize, GSM_BYTES);
    cudaFuncSetAttribute(mma_gemm2<2>, cudaFuncAttributeMaxDynamicSharedMemorySize, GSM_BYTES);
    cudaFuncSetAttribute(mma_gemm2<3>, cudaFuncAttributeMaxDynamicSharedMemorySize, GSM_BYTES);

    split_kernel<<<dim3(256, 5), 256>>>(x, Wq, Wk, Wv, Wo);

    dim3 gg(32, 8);
    mma_gemm2<0><<<gg, 256, GSM_BYTES>>>(bq, nullptr);
    mma_gemm2<1><<<gg, 256, GSM_BYTES>>>(bk, nullptr);
    mma_gemm2<2><<<gg, 256, GSM_BYTES>>>(bv, nullptr);

    pos_kernel<<<dim3(T_, NH_), 128>>>(rel);

    attn_mma<<<dim3(T_ / 32, NH_, 2), 256, SMEM_BYTES>>>();

    mma_gemm2<3><<<gg, 256, GSM_BYTES>>>(bo, out);
}

// round 15
// speedup vs baseline: 1.3857x; 1.0274x over previous
#include <cuda_runtime.h>
#include <cuda_bf16.h>
#include <cstdint>
#include <math.h>

#define B_   8
#define T_   512
#define D_   512
#define NH_  8
#define DH_  64

#define PLANE_ELEMS (B_ * NH_ * T_ * DH_)
__device__ __nv_bfloat16 g_Qh[PLANE_ELEMS], g_Ql[PLANE_ELEMS];   // [b][h][t][d], pre-scaled 1/8
__device__ __nv_bfloat16 g_Kh[PLANE_ELEMS], g_Kl[PLANE_ELEMS];   // [b][h][t][d]
__device__ __nv_bfloat16 g_VTh[PLANE_ELEMS], g_VTl[PLANE_ELEMS]; // [b][h][d][t]
__device__ float g_pos[NH_ * T_ * B_ * T_];                      // [h][t][b][s]

__device__ __nv_bfloat16 g_Xh[4096 * 512], g_Xl[4096 * 512];
__device__ __nv_bfloat16 g_CXh[4096 * 512], g_CXl[4096 * 512];
__device__ __nv_bfloat16 g_Wqh[512 * 512], g_Wql[512 * 512];
__device__ __nv_bfloat16 g_Wkh[512 * 512], g_Wkl[512 * 512];
__device__ __nv_bfloat16 g_Wvh[512 * 512], g_Wvl[512 * 512];
__device__ __nv_bfloat16 g_Woh[512 * 512], g_Wol[512 * 512];

__device__ __forceinline__ void cp16(unsigned smem_addr, const void* g) {
    asm volatile("cp.async.cg.shared.global [%0], [%1], 16;\n" :: "r"(smem_addr), "l"(g));
}
__device__ __forceinline__ void cp_commit() { asm volatile("cp.async.commit_group;\n"); }
template <int N> __device__ __forceinline__ void cp_wait() {
    asm volatile("cp.async.wait_group %0;\n" :: "n"(N));
}
__device__ __forceinline__ unsigned pack2(__nv_bfloat16 x, __nv_bfloat16 y) {
    __nv_bfloat162 t; t.x = x; t.y = y;
    return *reinterpret_cast<unsigned*>(&t);
}
__device__ __forceinline__ void split2(float x, float y, unsigned& hi, unsigned& lo) {
    __nv_bfloat16 xh = __float2bfloat16(x), yh = __float2bfloat16(y);
    hi = pack2(xh, yh);
    lo = pack2(__float2bfloat16(x - __bfloat162float(xh)),
               __float2bfloat16(y - __bfloat162float(yh)));
}
__device__ __forceinline__ void mma16816(float& c0, float& c1, float& c2, float& c3,
                                         unsigned a0, unsigned a1, unsigned a2, unsigned a3,
                                         unsigned b0, unsigned b1) {
    asm volatile("mma.sync.aligned.m16n8k16.row.col.f32.bf16.bf16.f32 "
                 "{%0,%1,%2,%3},{%4,%5,%6,%7},{%8,%9},{%0,%1,%2,%3};\n"
                 : "+f"(c0), "+f"(c1), "+f"(c2), "+f"(c3)
                 : "r"(a0), "r"(a1), "r"(a2), "r"(a3), "r"(b0), "r"(b1));
}

// ---------------------------------------------------------------------------
// split x + 4 weights into bf16 hi/lo planes (once)
// ---------------------------------------------------------------------------
__global__ __launch_bounds__(256) void split_kernel(const float* __restrict__ x,
                                                    const float* __restrict__ Wq,
                                                    const float* __restrict__ Wk,
                                                    const float* __restrict__ Wv,
                                                    const float* __restrict__ Wo) {
    const int seg = blockIdx.y;
    const float* src;
    __nv_bfloat16 *dh, *dl;
    int n;
    if (seg == 0)      { src = x;  dh = g_Xh;  dl = g_Xl;  n = 4096 * 512 / 2; }
    else if (seg == 1) { src = Wq; dh = g_Wqh; dl = g_Wql; n = 512 * 512 / 2; }
    else if (seg == 2) { src = Wk; dh = g_Wkh; dl = g_Wkl; n = 512 * 512 / 2; }
    else if (seg == 3) { src = Wv; dh = g_Wvh; dl = g_Wvl; n = 512 * 512 / 2; }
    else               { src = Wo; dh = g_Woh; dl = g_Wol; n = 512 * 512 / 2; }
    for (int i = blockIdx.x * 256 + threadIdx.x; i < n; i += gridDim.x * 256) {
        float2 v = ((const float2*)src)[i];
        unsigned hi, lo;
        split2(v.x, v.y, hi, lo);
        ((unsigned*)dh)[i] = hi;
        ((unsigned*)dl)[i] = lo;
    }
}

// ---------------------------------------------------------------------------
// bf16-plane GEMM (R10-proven version; scalar fragment loads)
// ---------------------------------------------------------------------------
#define GA_STR 72
#define GA_PLB (128 * GA_STR * 2)
#define SA_BUF (2 * GA_PLB)
#define GW_PLB (64 * GA_STR * 2)
#define SW_BUF (2 * GW_PLB)
#define SW_B   (2 * SA_BUF)
#define GSM_BYTES (SW_B + 2 * SW_BUF)

template <int DST>
__global__ __launch_bounds__(256) void mma_gemm2(const float* __restrict__ bias,
                                                 float* __restrict__ Cout) {
    extern __shared__ char gsm[];
    const unsigned sb = (unsigned)__cvta_generic_to_shared(gsm);

    const __nv_bfloat16 *Aph, *Apl, *Wph, *Wpl;
    if (DST == 3) { Aph = g_CXh; Apl = g_CXl; } else { Aph = g_Xh; Apl = g_Xl; }
    if (DST == 0)      { Wph = g_Wqh; Wpl = g_Wql; }
    else if (DST == 1) { Wph = g_Wkh; Wpl = g_Wkl; }
    else if (DST == 2) { Wph = g_Wvh; Wpl = g_Wvl; }
    else               { Wph = g_Woh; Wpl = g_Wol; }

    const int i0 = blockIdx.x * 128, j0 = blockIdx.y * 64;
    const int tid = threadIdx.x;
    const int wid = tid >> 5, lane = tid & 31;
    const int wm = wid & 1, wn = wid >> 1;
    const int grp = lane >> 2, q = lane & 3;

    auto issue = [&](int st, int buf) {
        const int k0 = st * 64;
        for (int c = tid; c < 2048; c += 256) {
            int col8 = c & 7, row = (c >> 3) & 127, pl = c >> 10;
            const __nv_bfloat16* src = (pl ? Apl : Aph) + (size_t)(i0 + row) * 512 + k0 + col8 * 8;
            cp16(sb + buf * SA_BUF + pl * GA_PLB + (row * GA_STR + col8 * 8) * 2, src);
        }
        for (int c = tid; c < 1024; c += 256) {
            int col8 = c & 7, row = (c >> 3) & 63, pl = c >> 9;
            const __nv_bfloat16* src = (pl ? Wpl : Wph) + (size_t)(j0 + row) * 512 + k0 + col8 * 8;
            cp16(sb + SW_B + buf * SW_BUF + pl * GW_PLB + (row * GA_STR + col8 * 8) * 2, src);
        }
    };

    issue(0, 0); cp_commit();
    issue(1, 1); cp_commit();

    float acc[4][2][4];
#pragma unroll
    for (int a = 0; a < 4; a++)
#pragma unroll
        for (int b = 0; b < 2; b++)
#pragma unroll
            for (int c = 0; c < 4; c++) acc[a][b][c] = 0.f;

    for (int st = 0; st < 8; st++) {
        const int buf = st & 1;
        if (st == 7) cp_wait<0>(); else cp_wait<1>();
        __syncthreads();

        const char* Ab = gsm + buf * SA_BUF;
        const char* Wb = gsm + SW_B + buf * SW_BUF;
#pragma unroll
        for (int k16 = 0; k16 < 4; k16++) {
            const int ko = k16 * 16 + 2 * q;
            unsigned bh[2][2], bl[2][2];
#pragma unroll
            for (int nf = 0; nf < 2; nf++) {
                const int jl = wn * 16 + nf * 8 + grp;
                const char* wp = Wb + (jl * GA_STR + ko) * 2;
                bh[nf][0] = *(const unsigned*)wp;
                bh[nf][1] = *(const unsigned*)(wp + 16);
                bl[nf][0] = *(const unsigned*)(wp + GW_PLB);
                bl[nf][1] = *(const unsigned*)(wp + GW_PLB + 16);
            }
#pragma unroll
            for (int mf = 0; mf < 4; mf++) {
                const int row = wm * 64 + mf * 16 + grp;
                const char* ap = Ab + (row * GA_STR + ko) * 2;
                unsigned a0 = *(const unsigned*)ap;
                unsigned a1 = *(const unsigned*)(ap + 8 * GA_STR * 2);
                unsigned a2 = *(const unsigned*)(ap + 16);
                unsigned a3 = *(const unsigned*)(ap + 8 * GA_STR * 2 + 16);
                unsigned c0 = *(const unsigned*)(ap + GA_PLB);
                unsigned c1 = *(const unsigned*)(ap + GA_PLB + 8 * GA_STR * 2);
                unsigned c2 = *(const unsigned*)(ap + GA_PLB + 16);
                unsigned c3 = *(const unsigned*)(ap + GA_PLB + 8 * GA_STR * 2 + 16);
#pragma unroll
                for (int nf = 0; nf < 2; nf++) {
                    mma16816(acc[mf][nf][0], acc[mf][nf][1], acc[mf][nf][2], acc[mf][nf][3],
                             a0, a1, a2, a3, bh[nf][0], bh[nf][1]);
                    mma16816(acc[mf][nf][0], acc[mf][nf][1], acc[mf][nf][2], acc[mf][nf][3],
                             a0, a1, a2, a3, bl[nf][0], bl[nf][1]);
                    mma16816(acc[mf][nf][0], acc[mf][nf][1], acc[mf][nf][2], acc[mf][nf][3],
                             c0, c1, c2, c3, bh[nf][0], bh[nf][1]);
                }
            }
        }
        __syncthreads();
        if (st + 2 < 8) issue(st + 2, buf);
        cp_commit();
    }

#pragma unroll
    for (int mf = 0; mf < 4; mf++) {
#pragma unroll
        for (int nf = 0; nf < 2; nf++) {
#pragma unroll
            for (int half = 0; half < 2; half++) {
                const int i = i0 + wm * 64 + mf * 16 + grp + half * 8;
                const int j = j0 + wn * 16 + nf * 8 + 2 * q;
                float v0 = acc[mf][nf][half * 2]     + bias[j];
                float v1 = acc[mf][nf][half * 2 + 1] + bias[j + 1];
                if (DST == 3) {
                    *(float2*)&Cout[(size_t)i * 512 + j] = make_float2(v0, v1);
                    continue;
                }
                if (DST == 0) { v0 *= 0.125f; v1 *= 0.125f; }
                const int b = i >> 9, t = i & 511;
                const int hh = j >> 6, dh = j & 63;
                unsigned hi, lo;
                split2(v0, v1, hi, lo);
                if (DST == 0) {
                    size_t o = ((size_t)(b * NH_ + hh) * T_ + t) * 64 + dh;
                    *(unsigned*)&g_Qh[o] = hi; *(unsigned*)&g_Ql[o] = lo;
                } else if (DST == 1) {
                    size_t o = ((size_t)(b * NH_ + hh) * T_ + t) * 64 + dh;
                    *(unsigned*)&g_Kh[o] = hi; *(unsigned*)&g_Kl[o] = lo;
                } else {
                    __nv_bfloat16 h0 = __float2bfloat16(v0);
                    __nv_bfloat16 h1 = __float2bfloat16(v1);
                    size_t o = ((size_t)(b * NH_ + hh) * 64 + dh) * T_ + t;
                    g_VTh[o]       = h0;
                    g_VTh[o + T_]  = h1;
                    g_VTl[o]       = __float2bfloat16(v0 - __bfloat162float(h0));
                    g_VTl[o + T_]  = __float2bfloat16(v1 - __bfloat162float(h1));
                }
            }
        }
    }
}

// ---------------------------------------------------------------------------
// pos kernel (unchanged)
// ---------------------------------------------------------------------------
#define PR_STR 68
#define PTILE  (64 * PR_STR)

__global__ __launch_bounds__(128) void pos_kernel(const float* __restrict__ rel) {
    __shared__ float Rs[2 * PTILE];
    const int t = blockIdx.x, h = blockIdx.y;
    const int tid = threadIdx.x;
    const int wid = tid >> 5, lane = tid & 31;
    const int grp = lane >> 2, q = lane & 3;
    const unsigned sb = (unsigned)__cvta_generic_to_shared(Rs);

    unsigned Bh[4][2], Bl[4][2];
#pragma unroll
    for (int kk = 0; kk < 4; kk++) {
        size_t base = ((size_t)(grp*NH_+h)*T_ + t)*64 + kk*16 + 2*q;
        Bh[kk][0] = *(const unsigned*)&g_Qh[base];
        Bh[kk][1] = *(const unsigned*)&g_Qh[base + 8];
        Bl[kk][0] = *(const unsigned*)&g_Ql[base];
        Bl[kk][1] = *(const unsigned*)&g_Ql[base + 8];
    }

    auto issue = [&](int blk, int buf) {
        const float* base = rel + ((size_t)t*T_ + blk*64)*D_ + h*64;
#pragma unroll
        for (int p = 0; p < 8; p++) {
            int c = tid + p * 128;
            int row = c >> 4, col4 = c & 15;
            cp16(sb + (unsigned)(buf*PTILE + row*PR_STR + col4*4)*4,
                 base + (size_t)row*D_ + col4*4);
        }
    };

    issue(0, 0); cp_commit();
    issue(1, 1); cp_commit();

    for (int blk = 0; blk < 8; blk++) {
        const int buf = blk & 1;
        if (blk == 7) cp_wait<0>(); else cp_wait<1>();
        __syncthreads();

        const float* rs = Rs + buf*PTILE + (wid*16 + grp)*PR_STR;
        float c0 = 0.f, c1 = 0.f, c2 = 0.f, c3 = 0.f;
#pragma unroll
        for (int kk = 0; kk < 4; kk++) {
            float2 rA0 = *(const float2*)(rs + kk*16 + 2*q);
            float2 rA2 = *(const float2*)(rs + kk*16 + 2*q + 8);
            float2 rA1 = *(const float2*)(rs + 8*PR_STR + kk*16 + 2*q);
            float2 rA3 = *(const float2*)(rs + 8*PR_STR + kk*16 + 2*q + 8);
            unsigned ah0, al0, ah1, al1, ah2, al2, ah3, al3;
            split2(rA0.x, rA0.y, ah0, al0);
            split2(rA1.x, rA1.y, ah1, al1);
            split2(rA2.x, rA2.y, ah2, al2);
            split2(rA3.x, rA3.y, ah3, al3);
            mma16816(c0,c1,c2,c3, ah0,ah1,ah2,ah3, Bh[kk][0], Bh[kk][1]);
            mma16816(c0,c1,c2,c3, ah0,ah1,ah2,ah3, Bl[kk][0], Bl[kk][1]);
            mma16816(c0,c1,c2,c3, al0,al1,al2,al3, Bh[kk][0], Bh[kk][1]);
        }
        const int s0 = blk * 64 + wid * 16;
        size_t o = ((size_t)h*T_ + t) * B_;
        g_pos[(o + 2*q    )*T_ + s0 + grp    ] = c0;
        g_pos[(o + 2*q + 1)*T_ + s0 + grp    ] = c1;
        g_pos[(o + 2*q    )*T_ + s0 + grp + 8] = c2;
        g_pos[(o + 2*q + 1)*T_ + s0 + grp + 8] = c3;

        __syncthreads();
        if (blk + 2 < 8) issue(blk + 2, buf);
        cp_commit();
    }
}

// ---------------------------------------------------------------------------
// FA2 attention, batch-split CTAs (unchanged from R14)
// ---------------------------------------------------------------------------
#define KS_B   0
#define KBUF_B 18432
#define KPL_B  9216
#define VS_B   36864
#define VBUF_B 24576
#define VPL_B  12288
#define PS_B   86016
#define PBUF_B 8192
#define SMEM_BYTES 102400

__global__ __launch_bounds__(256, 2) void attn_mma() {
    const int h  = blockIdx.y;
    const int t0 = blockIdx.x * 32;
    const int bg = blockIdx.z;
    extern __shared__ char sm[];
    const unsigned sb = (unsigned)__cvta_generic_to_shared(sm);

    const int tid = threadIdx.x;
    const int wid = tid >> 5;
    const int lane = tid & 31;
    const int grp = lane >> 2, q = lane & 3;
    const int b4 = wid & 3, mt = wid >> 2;
    const int b = bg * 4 + b4;

    unsigned QAh[4][4], QAl[4][4];
#pragma unroll
    for (int kk = 0; kk < 4; kk++) {
        size_t base = ((size_t)(b*NH_+h)*T_ + t0 + mt*16 + grp)*64 + kk*16 + 2*q;
        QAh[kk][0] = *(const unsigned*)&g_Qh[base];
        QAh[kk][1] = *(const unsigned*)&g_Qh[base + 8*64];
        QAh[kk][2] = *(const unsigned*)&g_Qh[base + 8];
        QAh[kk][3] = *(const unsigned*)&g_Qh[base + 8*64 + 8];
        QAl[kk][0] = *(const unsigned*)&g_Ql[base];
        QAl[kk][1] = *(const unsigned*)&g_Ql[base + 8*64];
        QAl[kk][2] = *(const unsigned*)&g_Ql[base + 8];
        QAl[kk][3] = *(const unsigned*)&g_Ql[base + 8*64 + 8];
    }

    auto issue_tile = [&](int s0, int buf) {
        for (int i = tid; i < 1024; i += 256) {
            int q4 = i & 7, row = i >> 3;
            int s = row & 15, bb = (row >> 4) & 3, pl = row >> 6;
            const __nv_bfloat16* src =
                (pl ? g_Kl : g_Kh) + ((size_t)((bg*4+bb)*NH_+h)*T_ + s0 + s)*64 + q4*8;
            cp16(sb + KS_B + buf*KBUF_B + pl*KPL_B + (bb*16 + s)*144 + q4*16, src);
        }
        for (int i = tid; i < 1024; i += 256) {
            int q4 = i & 1, row = i >> 1;
            int d = row & 63, bb = (row >> 6) & 3, pl = row >> 8;
            const __nv_bfloat16* src =
                (pl ? g_VTl : g_VTh) + ((size_t)((bg*4+bb)*NH_+h)*64 + d)*T_ + s0 + q4*8;
            cp16(sb + VS_B + buf*VBUF_B + pl*VPL_B + (bb*64 + d)*48 + q4*16, src);
        }
        for (int i = tid; i < 512; i += 256) {
            int q4 = i & 3, row = i >> 2;
            int t = row & 31, bb = row >> 5;
            const float* src = g_pos + ((size_t)(h*T_ + t0 + t)*B_ + bg*4 + bb)*T_ + s0 + q4*4;
            cp16(sb + PS_B + buf*PBUF_B + (bb*32 + t)*64 + q4*16, src);
        }
    };

    issue_tile(0, 0);  cp_commit();
    issue_tile(16, 1); cp_commit();

    float ctx[8][4];
#pragma unroll
    for (int nt = 0; nt < 8; nt++)
#pragma unroll
        for (int i = 0; i < 4; i++) ctx[nt][i] = 0.f;
    float m_a = -1e30f, m_b = -1e30f, l_a = 0.f, l_b = 0.f;

    for (int it = 0; it < 32; it++) {
        const int buf = it & 1;
        if (it == 31) cp_wait<0>(); else cp_wait<1>();
        __syncthreads();

        float sg[2][4];
        const float* pp = (const float*)(sm + PS_B + buf*PBUF_B) + (b4*32 + mt*16 + grp)*16;
#pragma unroll
        for (int ng = 0; ng < 2; ng++) {
            float2 pa = *(const float2*)(pp + ng*8 + 2*q);
            float2 pb = *(const float2*)(pp + 8*16 + ng*8 + 2*q);
            float c0 = pa.x, c1 = pa.y, c2 = pb.x, c3 = pb.y;
#pragma unroll
            for (int kk = 0; kk < 4; kk++) {
                const char* kp = sm + KS_B + buf*KBUF_B + (b4*16 + ng*8 + grp)*144 + kk*32 + q*4;
                unsigned bh0 = *(const unsigned*)kp;
                unsigned bh1 = *(const unsigned*)(kp + 16);
                unsigned bl0 = *(const unsigned*)(kp + KPL_B);
                unsigned bl1 = *(const unsigned*)(kp + KPL_B + 16);
                mma16816(c0,c1,c2,c3, QAh[kk][0],QAh[kk][1],QAh[kk][2],QAh[kk][3], bh0, bh1);
                mma16816(c0,c1,c2,c3, QAh[kk][0],QAh[kk][1],QAh[kk][2],QAh[kk][3], bl0, bl1);
                mma16816(c0,c1,c2,c3, QAl[kk][0],QAl[kk][1],QAl[kk][2],QAl[kk][3], bh0, bh1);
            }
            sg[ng][0] = c0; sg[ng][1] = c1; sg[ng][2] = c2; sg[ng][3] = c3;
        }

        float ma = fmaxf(fmaxf(sg[0][0], sg[0][1]), fmaxf(sg[1][0], sg[1][1]));
        float mb = fmaxf(fmaxf(sg[0][2], sg[0][3]), fmaxf(sg[1][2], sg[1][3]));
        ma = fmaxf(ma, __shfl_xor_sync(0xffffffffu, ma, 1, 4));
        ma = fmaxf(ma, __shfl_xor_sync(0xffffffffu, ma, 2, 4));
        mb = fmaxf(mb, __shfl_xor_sync(0xffffffffu, mb, 1, 4));
        mb = fmaxf(mb, __shfl_xor_sync(0xffffffffu, mb, 2, 4));
        float mna = fmaxf(m_a, ma), mnb = fmaxf(m_b, mb);
        float sca = __expf(m_a - mna), scb = __expf(m_b - mnb);
        float pa0 = __expf(sg[0][0] - mna), pa1 = __expf(sg[0][1] - mna);
        float pa2 = __expf(sg[1][0] - mna), pa3 = __expf(sg[1][1] - mna);
        float pb0 = __expf(sg[0][2] - mnb), pb1 = __expf(sg[0][3] - mnb);
        float pb2 = __expf(sg[1][2] - mnb), pb3 = __expf(sg[1][3] - mnb);
        float la = pa0 + pa1 + pa2 + pa3;
        float lb = pb0 + pb1 + pb2 + pb3;
        la += __shfl_xor_sync(0xffffffffu, la, 1, 4);
        la += __shfl_xor_sync(0xffffffffu, la, 2, 4);
        lb += __shfl_xor_sync(0xffffffffu, lb, 1, 4);
        lb += __shfl_xor_sync(0xffffffffu, lb, 2, 4);
        l_a = l_a * sca + la; l_b = l_b * scb + lb;
        m_a = mna; m_b = mnb;

        unsigned ah0, al0, ah1, al1, ah2, al2, ah3, al3;
        split2(pa0, pa1, ah0, al0);
        split2(pb0, pb1, ah1, al1);
        split2(pa2, pa3, ah2, al2);
        split2(pb2, pb3, ah3, al3);

#pragma unroll
        for (int nt = 0; nt < 8; nt++) {
            ctx[nt][0] *= sca; ctx[nt][1] *= sca;
            ctx[nt][2] *= scb; ctx[nt][3] *= scb;
        }
#pragma unroll
        for (int nt = 0; nt < 8; nt++) {
            const char* vp = sm + VS_B + buf*VBUF_B + (b4*64 + nt*8 + grp)*48 + q*4;
            unsigned bh0 = *(const unsigned*)vp;
            unsigned bh1 = *(const unsigned*)(vp + 16);
            unsigned bl0 = *(const unsigned*)(vp + VPL_B);
            unsigned bl1 = *(const unsigned*)(vp + VPL_B + 16);
            mma16816(ctx[nt][0],ctx[nt][1],ctx[nt][2],ctx[nt][3], ah0,ah1,ah2,ah3, bh0, bh1);
            mma16816(ctx[nt][0],ctx[nt][1],ctx[nt][2],ctx[nt][3], al0,al1,al2,al3, bh0, bh1);
            mma16816(ctx[nt][0],ctx[nt][1],ctx[nt][2],ctx[nt][3], ah0,ah1,ah2,ah3, bl0, bl1);
        }

        __syncthreads();
        if (it + 2 < 32) issue_tile((it + 2) * 16, buf);
        cp_commit();
    }

    const float inva = 1.0f / l_a, invb = 1.0f / l_b;
    size_t r0 = ((size_t)b*T_ + t0 + mt*16 + grp)*512 + h*64 + 2*q;
    size_t r1 = r0 + 8 * 512;
#pragma unroll
    for (int nt = 0; nt < 8; nt++) {
        unsigned hi, lo;
        split2(ctx[nt][0]*inva, ctx[nt][1]*inva, hi, lo);
        *(unsigned*)&g_CXh[r0 + nt*8] = hi;
        *(unsigned*)&g_CXl[r0 + nt*8] = lo;
        split2(ctx[nt][2]*invb, ctx[nt][3]*invb, hi, lo);
        *(unsigned*)&g_CXh[r1 + nt*8] = hi;
        *(unsigned*)&g_CXl[r1 + nt*8] = lo;
    }
}

// ---------------------------------------------------------------------------
extern "C" void kernel_launch(void* const* d_in, const int* in_sizes, int n_in,
                              void* d_out, int out_size) {
    const float* x   = (const float*)d_in[0];
    const float* rel = (const float*)d_in[1];
    const float* Wq  = (const float*)d_in[2];
    const float* bq  = (const float*)d_in[3];
    const float* Wk  = (const float*)d_in[4];
    const float* bk  = (const float*)d_in[5];
    const float* Wv  = (const float*)d_in[6];
    const float* bv  = (const float*)d_in[7];
    const float* Wo  = (const float*)d_in[8];
    const float* bo  = (const float*)d_in[9];
    float* out = (float*)d_out;

    cudaFuncSetAttribute(attn_mma, cudaFuncAttributeMaxDynamicSharedMemorySize, SMEM_BYTES);
    cudaFuncSetAttribute(mma_gemm2<0>, cudaFuncAttributeMaxDynamicSharedMemorySize, GSM_BYTES);
    cudaFuncSetAttribute(mma_gemm2<1>, cudaFuncAttributeMaxDynamicSharedMemorySize, GSM_BYTES);
    cudaFuncSetAttribute(mma_gemm2<2>, cudaFuncAttributeMaxDynamicSharedMemorySize, GSM_BYTES);
    cudaFuncSetAttribute(mma_gemm2<3>, cudaFuncAttributeMaxDynamicSharedMemorySize, GSM_BYTES);

    // Lazily-created side stream + events (host-side objects; same work every call)
    static cudaStream_t s_side = nullptr;
    static cudaEvent_t  s_fork = nullptr, s_join = nullptr;
    if (!s_side) {
        cudaStreamCreateWithFlags(&s_side, cudaStreamNonBlocking);
        cudaEventCreateWithFlags(&s_fork, cudaEventDisableTiming);
        cudaEventCreateWithFlags(&s_join, cudaEventDisableTiming);
    }

    split_kernel<<<dim3(256, 5), 256>>>(x, Wq, Wk, Wv, Wo);

    dim3 gg(32, 8);
    mma_gemm2<0><<<gg, 256, GSM_BYTES>>>(bq, nullptr);   // Q planes (pos + attn dep)

    // Fork: pos (DRAM-bound) on side stream, K/V GEMMs (tensor-bound) on main
    cudaEventRecord(s_fork, 0);
    cudaStreamWaitEvent(s_side, s_fork, 0);
    pos_kernel<<<dim3(T_, NH_), 128, 0, s_side>>>(rel);
    cudaEventRecord(s_join, s_side);

    mma_gemm2<1><<<gg, 256, GSM_BYTES>>>(bk, nullptr);
    mma_gemm2<2><<<gg, 256, GSM_BYTES>>>(bv, nullptr);

    // Join: attn needs K, V (main) and pos (side)
    cudaStreamWaitEvent(0, s_join, 0);

    attn_mma<<<dim3(T_ / 32, NH_, 2), 256, SMEM_BYTES>>>();

    mma_gemm2<3><<<gg, 256, GSM_BYTES>>>(bo, out);
}